// round 13
// baseline (speedup 1.0000x reference)
#include <cuda_runtime.h>
#include <cstdint>

#define N_NODESC 100000
#define N_EDGESC 1600000
#define N_GRAPHSC 512
#define F_INC 64
#define HC 128
#define H3C 384
#define STEPSC 6
#define NTILES 782                         // ceil(100000/128)
#define AIMG_WORDS ((size_t)NTILES * 8 * 1024)
#define BIMG_KT_W 768                      // 12 n-blocks x 64 words
#define BIMG_STEP_W (4 * 16 * BIMG_KT_W)   // 49152 words per step per image
#define STAGE_W 7168                       // Ahi 2048 | Alo 2048 | Bhi 1536 | Blo 1536
#define SMEM_DYN (3 * STAGE_W * 4)         // 86016 B
#define NSCANB 98                          // ceil(100000/1024)

// ---------------- device scratch ----------------
__device__ float g_hA[(size_t)N_NODESC * HC];
__device__ float g_hB[(size_t)N_NODESC * HC];
__device__ float g_WcG[(size_t)STEPSC * H3C * HC];
__device__ __align__(16) uint32_t g_AHi[AIMG_WORDS];     // agg fragment image (bf16x2 hi)
__device__ __align__(16) uint32_t g_ALo[AIMG_WORDS];
__device__ __align__(16) uint32_t g_HHi[2][AIMG_WORDS];  // h fragment images, step parity
__device__ __align__(16) uint32_t g_HLo[2][AIMG_WORDS];
__device__ __align__(16) uint32_t g_BHi[(size_t)STEPSC * BIMG_STEP_W];
__device__ __align__(16) uint32_t g_BLo[(size_t)STEPSC * BIMG_STEP_W];
__device__ float g_sums[N_GRAPHSC * HC];
__device__ float g_cnt[N_GRAPHSC];
__device__ int   g_is64;
// CSR
__device__ int g_deg[N_NODESC];
__device__ int g_cursor[N_NODESC];
__device__ int g_rowstart[N_NODESC + 1];
__device__ int g_srcs[N_EDGESC];
__device__ int g_bsum[NSCANB];

// ---------------- helpers ----------------
__device__ __forceinline__ uint32_t smem_u32(const void* p) {
    uint32_t a;
    asm("{ .reg .u64 t; cvta.to.shared.u64 t, %1; cvt.u32.u64 %0, t; }" : "=r"(a) : "l"(p));
    return a;
}
__device__ __forceinline__ uint32_t pack_bf2(float lo, float hi) {
    uint32_t r;
    asm("cvt.rn.bf16x2.f32 %0, %1, %2;" : "=r"(r) : "f"(hi), "f"(lo));
    return r;
}
__device__ __forceinline__ float bf2_low(uint32_t v)  { return __uint_as_float(v << 16); }
__device__ __forceinline__ float bf2_high(uint32_t v) { return __uint_as_float(v & 0xffff0000u); }
__device__ __forceinline__ void pack_pair(float v0, float v1, uint32_t& hi, uint32_t& lo) {
    hi = pack_bf2(v0, v1);
    lo = pack_bf2(v0 - bf2_low(hi), v1 - bf2_high(hi));
}
__device__ __forceinline__ void red4(float* p, float4 v) {
    asm volatile("red.global.add.v4.f32 [%0], {%1,%2,%3,%4};"
                 :: "l"(p), "f"(v.x), "f"(v.y), "f"(v.z), "f"(v.w) : "memory");
}
__device__ __forceinline__ int load_idx(const void* p, long long i, int is64) {
    if (is64) return (int)((const long long*)p)[i];
    return ((const int*)p)[i];
}
__device__ __forceinline__ float sigf(float x) {
    return __fdividef(1.0f, 1.0f + __expf(-x));
}
__device__ __forceinline__ float tanhfast(float x) {
    float e = __expf(2.0f * x);
    return 1.0f - __fdividef(2.0f, e + 1.0f);
}
__device__ __forceinline__ void mma_bf16(float* d, uint32_t a0, uint32_t a1, uint32_t a2,
                                         uint32_t a3, uint32_t b0, uint32_t b1) {
    asm volatile(
        "mma.sync.aligned.m16n8k16.row.col.f32.bf16.bf16.f32 "
        "{%0,%1,%2,%3}, {%4,%5,%6,%7}, {%8,%9}, {%0,%1,%2,%3};"
        : "+f"(d[0]), "+f"(d[1]), "+f"(d[2]), "+f"(d[3])
        : "r"(a0), "r"(a1), "r"(a2), "r"(a3), "r"(b0), "r"(b1));
}
__device__ __forceinline__ void mma3(float* d, const uint4& ah, const uint4& al,
                                     const uint2& bh, const uint2& bl) {
    mma_bf16(d, ah.x, ah.y, ah.z, ah.w, bh.x, bh.y);
    mma_bf16(d, ah.x, ah.y, ah.z, ah.w, bl.x, bl.y);
    mma_bf16(d, al.x, al.y, al.z, al.w, bh.x, bh.y);
}
__device__ __forceinline__ void cpasync16(uint32_t saddr, const void* g) {
    asm volatile("cp.async.cg.shared.global [%0], [%1], 16;" :: "r"(saddr), "l"(g) : "memory");
}
__device__ __forceinline__ void cp_commit() { asm volatile("cp.async.commit_group;" ::: "memory"); }
__device__ __forceinline__ void cp_wait1()  { asm volatile("cp.async.wait_group 1;" ::: "memory"); }
__device__ __forceinline__ void cp_wait0()  { asm volatile("cp.async.wait_group 0;" ::: "memory"); }

// Fragment-image word offset for (row-in-tile rr, pair p) within a 1024-word kt block.
__device__ __forceinline__ int aimg_word(int rr, int p) {
    int g = rr & 7, rh = (rr >> 3) & 1, rb = rr >> 4;
    return rb * 128 + (g * 4 + (p & 3)) * 4 + (p >> 2) * 2 + rh;
}

// Split a float4 into 2 hi + 2 lo bf16x2 words; store to image at pairs p0, p0+1.
__device__ __forceinline__ void store_split4(uint32_t* Hi, uint32_t* Lo, size_t base,
                                             int rr, int p0, float4 v) {
    uint32_t h0, l0, h1, l1;
    pack_pair(v.x, v.y, h0, l0);
    pack_pair(v.z, v.w, h1, l1);
    int w0 = aimg_word(rr, p0), w1 = aimg_word(rr, p0 + 1);
    Hi[base + w0] = h0; Hi[base + w1] = h1;
    Lo[base + w0] = l0; Lo[base + w1] = l1;
}

// ---------------- index dtype sniffer ----------------
__global__ void k_detect(const int* __restrict__ ei) {
    int any = 0;
    for (int i = threadIdx.x; i < 2048; i += blockDim.x) any |= ei[2 * i + 1];
    any = __syncthreads_or(any);
    if (threadIdx.x == 0) g_is64 = (any == 0) ? 1 : 0;
}

// ---------------- CSR build (deg + per-graph counts fused) ----------------
__global__ void k_deg(const void* __restrict__ ei, const void* __restrict__ batch) {
    int e = blockIdx.x * blockDim.x + threadIdx.x;
    if (e >= N_EDGESC) return;
    int is64 = g_is64;
    int d = load_idx(ei, (long long)N_EDGESC + e, is64);
    atomicAdd(&g_deg[d], 1);
    if (e < N_NODESC) atomicAdd(&g_cnt[load_idx(batch, e, is64)], 1.0f);
}

__global__ void k_scan1() {
    __shared__ int sred[8];
    int b = blockIdx.x, t = threadIdx.x;
    int i0 = b * 1024 + t * 4;
    int s = 0;
#pragma unroll
    for (int j = 0; j < 4; j++) {
        int i = i0 + j;
        if (i < N_NODESC) s += g_deg[i];
    }
#pragma unroll
    for (int o = 16; o > 0; o >>= 1) s += __shfl_down_sync(0xffffffffu, s, o);
    if ((t & 31) == 0) sred[t >> 5] = s;
    __syncthreads();
    if (t == 0) {
        int tot = 0;
#pragma unroll
        for (int j = 0; j < 8; j++) tot += sred[j];
        g_bsum[b] = tot;
    }
}

__global__ void k_scan2() {
    int lane = threadIdx.x;  // 32
    int base = 0;
    for (int c = 0; c < 4; c++) {
        int i = c * 32 + lane;
        int v = (i < NSCANB) ? g_bsum[i] : 0;
        int s = v;
#pragma unroll
        for (int o = 1; o < 32; o <<= 1) {
            int t = __shfl_up_sync(0xffffffffu, s, o);
            if (lane >= o) s += t;
        }
        if (i < NSCANB) g_bsum[i] = base + (s - v);  // exclusive
        base += __shfl_sync(0xffffffffu, s, 31);
    }
    if (lane == 0) g_rowstart[0] = 0;
}

__global__ void k_scan3() {
    __shared__ int swarp[8];
    int b = blockIdx.x, t = threadIdx.x;
    int i0 = b * 1024 + t * 4;
    int d[4], ts = 0;
#pragma unroll
    for (int j = 0; j < 4; j++) {
        d[j] = (i0 + j < N_NODESC) ? g_deg[i0 + j] : 0;
        ts += d[j];
    }
    int s = ts;
#pragma unroll
    for (int o = 1; o < 32; o <<= 1) {
        int v = __shfl_up_sync(0xffffffffu, s, o);
        if ((t & 31) >= o) s += v;
    }
    if ((t & 31) == 31) swarp[t >> 5] = s;
    __syncthreads();
    int wpre = 0;
    for (int j = 0; j < (t >> 5); j++) wpre += swarp[j];
    int run = g_bsum[b] + wpre + (s - ts);
#pragma unroll
    for (int j = 0; j < 4; j++) {
        run += d[j];
        if (i0 + j < N_NODESC) g_rowstart[i0 + j + 1] = run;
    }
}

__global__ void k_fill(const void* __restrict__ ei) {
    int e = blockIdx.x * blockDim.x + threadIdx.x;
    if (e >= N_EDGESC) return;
    int is64 = g_is64;
    int s = load_idx(ei, e, is64);
    int d = load_idx(ei, (long long)N_EDGESC + e, is64);
    int pos = g_rowstart[d] + atomicAdd(&g_cursor[d], 1);
    g_srcs[pos] = s;
}

// ---------------- gather (feature-halved): agg[n][hf*64..+64) = sum h[src] ----------------
// One pass per half keeps the h-half (25.6MB) + image-half (25.6MB) L2-resident.
// 512 threads = 16 warps = 16 consecutive nodes; lane owns feature pair hf*64 + 2*lane.
__global__ void __launch_bounds__(512) k_gather(const float* __restrict__ h, int hf) {
    __shared__ uint32_t stg[1024];  // hi [0,512) | lo [512,1024)
    int w = threadIdx.x >> 5, lane = threadIdx.x & 31;
    int n = blockIdx.x * 16 + w;    // always < N_NODESC (100000 = 6250*16)
    int beg = g_rowstart[n], end = g_rowstart[n + 1];
    const float* hb = h + hf * 64 + lane * 2;
    float2 a0 = make_float2(0.f, 0.f);
    float2 a1 = make_float2(0.f, 0.f);
    float2 a2 = make_float2(0.f, 0.f);
    float2 a3 = make_float2(0.f, 0.f);
    int i = beg;
    for (; i + 4 <= end; i += 4) {
        int s0 = __ldg(&g_srcs[i]);
        int s1 = __ldg(&g_srcs[i + 1]);
        int s2 = __ldg(&g_srcs[i + 2]);
        int s3 = __ldg(&g_srcs[i + 3]);
        float2 v0 = *(const float2*)(hb + (size_t)s0 * HC);
        float2 v1 = *(const float2*)(hb + (size_t)s1 * HC);
        float2 v2 = *(const float2*)(hb + (size_t)s2 * HC);
        float2 v3 = *(const float2*)(hb + (size_t)s3 * HC);
        a0.x += v0.x; a0.y += v0.y;
        a1.x += v1.x; a1.y += v1.y;
        a2.x += v2.x; a2.y += v2.y;
        a3.x += v3.x; a3.y += v3.y;
    }
    for (; i < end; i++) {
        int s0 = __ldg(&g_srcs[i]);
        float2 v0 = *(const float2*)(hb + (size_t)s0 * HC);
        a0.x += v0.x; a0.y += v0.y;
    }
    a0.x += a1.x; a0.y += a1.y;
    a2.x += a3.x; a2.y += a3.y;
    a0.x += a2.x; a0.y += a2.y;

    // stage packed pair: kt_local = lane>>3 (4 kt blocks this pass), p = lane&7
    {
        int g = w & 7, rh = (w >> 3) & 1;
        int ktl = lane >> 3, p = lane & 7;
        uint32_t hi, lo;
        pack_pair(a0.x, a0.y, hi, lo);
        int wd = (g * 4 + (p & 3)) * 4 + ((p >> 2) << 1) + rh;
        stg[ktl * 128 + wd] = hi;
        stg[512 + ktl * 128 + wd] = lo;
    }
    __syncthreads();

    // coalesced write-out: 128 hi uint4 + 128 lo uint4 (threads 256+ idle)
    int tile = blockIdx.x >> 3;
    int rb = blockIdx.x & 7;
    int t = threadIdx.x;
    if (t < 256) {
        int q = t & 127, ktq = q >> 5, w4 = q & 31;
        const uint4* src = (const uint4*)(stg + ((t < 128) ? 0 : 512));
        uint32_t* dst = (t < 128) ? g_AHi : g_ALo;
        *(uint4*)(dst + ((size_t)tile * 8 + hf * 4 + ktq) * 1024 + rb * 128 + w4 * 4) = src[q];
    }
}

// ---------------- weight precompute ----------------
__global__ void k_prep_wc(const float* __restrict__ Wmp, const float* __restrict__ Wih) {
    int idx = blockIdx.x * blockDim.x + threadIdx.x;
    if (idx >= STEPSC * H3C * HC) return;
    int k = idx % HC;
    int j = (idx / HC) % H3C;
    int s = idx / (HC * H3C);
    const float4* wm = (const float4*)(Wmp + ((size_t)s * HC + k) * HC);
    const float4* wi = (const float4*)(Wih + (size_t)j * HC);
    float acc = 0.f;
#pragma unroll
    for (int m = 0; m < HC / 4; m++) {
        float4 a = wm[m], b = wi[m];
        acc += a.x * b.x + a.y * b.y + a.z * b.z + a.w * b.w;
    }
    g_WcG[idx] = acc;
}

// B fragment images (phase-split): [s][ys][kt][nb' 0..11][lane][j].
__global__ void k_prep_bimg(const float* __restrict__ Whh) {
    int idx = blockIdx.x * blockDim.x + threadIdx.x;
    if (idx >= STEPSC * BIMG_STEP_W) return;
    int j = idx & 1;
    int lane = (idx >> 1) & 31;
    int t = idx >> 6;
    int nbp = t % 12; t /= 12;
    int kt = t % 16;  t /= 16;
    int ys = t % 4;
    int s = t / 4;
    int g = lane >> 2, tI = lane & 3;
    int k0 = kt * 16 + 2 * tI + 8 * j;
    float v[2];
#pragma unroll
    for (int e = 0; e < 2; e++) {
        int k = k0 + e;
        float val;
        if (nbp < 8) {
            int c = nbp * 8 + g;
            int f = ys * 32 + (c >> 1);
            int gate = c & 1;
            val = (k < HC) ? g_WcG[((size_t)s * H3C + gate * HC + f) * HC + k]
                           : Whh[(size_t)(gate * HC + f) * HC + (k - HC)];
        } else {
            int f = ys * 32 + (nbp - 8) * 8 + g;
            val = (k < HC) ? g_WcG[((size_t)s * H3C + 2 * HC + f) * HC + k]
                           : Whh[(size_t)(2 * HC + f) * HC + (k - HC)];
        }
        v[e] = val;
    }
    uint32_t hi, lo;
    pack_pair(v[0], v[1], hi, lo);
    g_BHi[idx] = hi;
    g_BLo[idx] = lo;
}

// ---------------- input layer: h = tanh(x @ W_in), fused fragment-image writes ----------------
__global__ void __launch_bounds__(256) k_input(
    const float* __restrict__ x, const float* __restrict__ Win, float* __restrict__ h,
    uint32_t* __restrict__ Hi, uint32_t* __restrict__ Lo)
{
    __shared__ float sw[F_INC * HC];  // [k][c], 32KB
    int tid = threadIdx.x;
    for (int i = tid; i < F_INC * HC; i += 256) sw[i] = Win[i];
    __syncthreads();
    int n = blockIdx.x * 256 + tid;
    if (n >= N_NODESC) return;

    float4 xr[16];
    const float4* xp = (const float4*)(x + (size_t)n * F_INC);
#pragma unroll
    for (int j = 0; j < 16; j++) xr[j] = xp[j];

    int tile = n >> 7, rr = n & 127;
    float* hrow = h + (size_t)n * HC;

#pragma unroll 1
    for (int cg = 0; cg < 8; cg++) {
        float acc[16];
#pragma unroll
        for (int j = 0; j < 16; j++) acc[j] = 0.f;
#pragma unroll
        for (int k4 = 0; k4 < 16; k4++) {
            float4 xv4 = xr[k4];
            float xs[4] = {xv4.x, xv4.y, xv4.z, xv4.w};
#pragma unroll
            for (int kk = 0; kk < 4; kk++) {
                int k = k4 * 4 + kk;
                const float4* wp = (const float4*)(sw + k * HC + cg * 16);
#pragma unroll
                for (int j4 = 0; j4 < 4; j4++) {
                    float4 w = wp[j4];
                    acc[j4 * 4 + 0] += xs[kk] * w.x;
                    acc[j4 * 4 + 1] += xs[kk] * w.y;
                    acc[j4 * 4 + 2] += xs[kk] * w.z;
                    acc[j4 * 4 + 3] += xs[kk] * w.w;
                }
            }
        }
        size_t base = ((size_t)tile * 8 + cg) * 1024;
#pragma unroll
        for (int j = 0; j < 4; j++) {
            float4 o;
            o.x = tanhf(acc[j * 4 + 0]);
            o.y = tanhf(acc[j * 4 + 1]);
            o.z = tanhf(acc[j * 4 + 2]);
            o.w = tanhf(acc[j * 4 + 3]);
            *(float4*)(hrow + cg * 16 + j * 4) = o;
            store_split4(Hi, Lo, base, rr, j * 2, o);
        }
    }
}

// ---------------- bf16x3 mma.sync fused GEMM + GRU, phase-split columns ----------------
__global__ void __launch_bounds__(256, 2) k_gemm(
    const float* __restrict__ hin, float* __restrict__ hout,
    const uint32_t* __restrict__ Bhi, const uint32_t* __restrict__ Blo,
    const uint32_t* __restrict__ HhiIn, const uint32_t* __restrict__ HloIn,
    uint32_t* __restrict__ HhiOut, uint32_t* __restrict__ HloOut,
    const float* __restrict__ bih, const float* __restrict__ bhh,
    const void* __restrict__ batch, int write_img)
{
    extern __shared__ uint32_t smu[];  // 3 stages x STAGE_W
    __shared__ float sbias[4][32];

    const int tid = threadIdx.x;
    const int lane = tid & 31;
    const int warp = tid >> 5;
    const int warpM = warp & 1;
    const int warpN = warp >> 1;
    const int tile = blockIdx.x;
    const int row0 = tile * 128;
    const int ys = blockIdx.y;

    if (tid < 32) {
        int f = ys * 32 + tid;
        sbias[0][tid] = bih[f] + bhh[f];
        sbias[1][tid] = bih[HC + f] + bhh[HC + f];
        sbias[2][tid] = bih[2 * HC + f];
        sbias[3][tid] = bhh[2 * HC + f];
    }

    const uint32_t* Bh = Bhi + (size_t)ys * 16 * BIMG_KT_W;
    const uint32_t* Bl = Blo + (size_t)ys * 16 * BIMG_KT_W;
    const uint32_t smem_base = smem_u32(smu);

    auto issue = [&](int c) {
        uint32_t d = smem_base + ((c % 3) * STAGE_W) * 4;
#pragma unroll
        for (int kk = 0; kk < 2; kk++) {
            int kt = 2 * c + kk;
            const uint32_t *ah, *al;
            if (kt < 8) {
                ah = g_AHi + ((size_t)tile * 8 + kt) * 1024;
                al = g_ALo + ((size_t)tile * 8 + kt) * 1024;
            } else {
                ah = HhiIn + ((size_t)tile * 8 + (kt - 8)) * 1024;
                al = HloIn + ((size_t)tile * 8 + (kt - 8)) * 1024;
            }
            cpasync16(d + kk * 4096 + tid * 16,        ah + tid * 4);
            cpasync16(d + 8192 + kk * 4096 + tid * 16, al + tid * 4);
            if (tid < 192) {
                cpasync16(d + 16384 + kk * 3072 + tid * 16, Bh + (size_t)kt * BIMG_KT_W + tid * 4);
                cpasync16(d + 22528 + kk * 3072 + tid * 16, Bl + (size_t)kt * BIMG_KT_W + tid * 4);
            }
        }
        cp_commit();
    };

    float acc_rz0[4][4], acc_rz1[4][4], acc_in[4][4], acc_hn[4][4];
#pragma unroll
    for (int mt = 0; mt < 4; mt++)
#pragma unroll
        for (int r = 0; r < 4; r++) {
            acc_rz0[mt][r] = 0.f; acc_rz1[mt][r] = 0.f;
            acc_in[mt][r] = 0.f;  acc_hn[mt][r] = 0.f;
        }

    issue(0);
    issue(1);

    for (int c = 0; c < 8; c++) {
        if (c < 7) cp_wait1();
        else cp_wait0();
        __syncthreads();
        if (c <= 5) issue(c + 2);

        const uint32_t* st = smu + (c % 3) * STAGE_W;
        bool ph0 = (c < 4);
#pragma unroll
        for (int kk = 0; kk < 2; kk++) {
            const uint32_t* Ahw = st + kk * 1024;
            const uint32_t* Alw = st + 2048 + kk * 1024;
            const uint32_t* Bhw = st + 4096 + kk * BIMG_KT_W;
            const uint32_t* Blw = st + 5632 + kk * BIMG_KT_W;

            uint2 rz0h = *(const uint2*)(Bhw + (2 * warpN) * 64 + lane * 2);
            uint2 rz0l = *(const uint2*)(Blw + (2 * warpN) * 64 + lane * 2);
            uint2 rz1h = *(const uint2*)(Bhw + (2 * warpN + 1) * 64 + lane * 2);
            uint2 rz1l = *(const uint2*)(Blw + (2 * warpN + 1) * 64 + lane * 2);
            uint2 xh   = *(const uint2*)(Bhw + (8 + warpN) * 64 + lane * 2);
            uint2 xl   = *(const uint2*)(Blw + (8 + warpN) * 64 + lane * 2);
#pragma unroll
            for (int mt = 0; mt < 4; mt++) {
                int rb = warpM * 4 + mt;
                uint4 ah = *(const uint4*)(Ahw + rb * 128 + lane * 4);
                uint4 al = *(const uint4*)(Alw + rb * 128 + lane * 4);
                mma3(acc_rz0[mt], ah, al, rz0h, rz0l);
                mma3(acc_rz1[mt], ah, al, rz1h, rz1l);
                if (ph0) mma3(acc_in[mt], ah, al, xh, xl);
                else     mma3(acc_hn[mt], ah, al, xh, xl);
            }
        }
    }
    __syncthreads();   // all compute done before sOut aliases pipeline smem

    // ---------------- fused GRU epilogue (phase-split layout) ----------------
    float* sOut = (float*)smu;  // [128][36]
    const int g = lane >> 2;
    const int tI = lane & 3;
    const bool use1 = (tI >= 2);

#pragma unroll
    for (int mt = 0; mt < 4; mt++) {
        int rowl = warpM * 64 + mt * 16 + g;
#pragma unroll
        for (int e = 0; e < 2; e++) {
            int u = 2 * tI + e;
            int src = g * 4 + (u & 3);
            float v0[4], v1[4];
#pragma unroll
            for (int i = 0; i < 4; i++) {
                v0[i] = __shfl_sync(0xffffffffu, acc_rz0[mt][i], src);
                v1[i] = __shfl_sync(0xffffffffu, acc_rz1[mt][i], src);
            }
            float Sr_a = use1 ? v1[0] : v0[0];
            float Sz_a = use1 ? v1[1] : v0[1];
            float Sr_b = use1 ? v1[2] : v0[2];
            float Sz_b = use1 ? v1[3] : v0[3];
            float in_a = acc_in[mt][e],     in_b = acc_in[mt][2 + e];
            float hn_a = acc_hn[mt][e],     hn_b = acc_hn[mt][2 + e];
            int fl = warpN * 8 + u;
            int fg = ys * 32 + fl;
            int growa = row0 + rowl, growb = growa + 8;
            float hpa = (growa < N_NODESC) ? hin[(size_t)growa * HC + fg] : 0.f;
            float hpb = (growb < N_NODESC) ? hin[(size_t)growb * HC + fg] : 0.f;
            float ra = sigf(Sr_a + sbias[0][fl]);
            float za = sigf(Sz_a + sbias[1][fl]);
            float na = tanhfast(in_a + sbias[2][fl] + ra * (hn_a + sbias[3][fl]));
            float rb2 = sigf(Sr_b + sbias[0][fl]);
            float zb = sigf(Sz_b + sbias[1][fl]);
            float nb2 = tanhfast(in_b + sbias[2][fl] + rb2 * (hn_b + sbias[3][fl]));
            sOut[rowl * 36 + fl]       = (1.f - za) * na + za * hpa;
            sOut[(rowl + 8) * 36 + fl] = (1.f - zb) * nb2 + zb * hpb;
        }
    }
    __syncthreads();

    // hout (fp32) writeback / pool accumulation
#pragma unroll
    for (int rep = 0; rep < 4; rep++) {
        int idx = tid + rep * 256;
        int row = idx >> 3, q = idx & 7;
        int grow = row0 + row;
        if (grow < N_NODESC) {
            float4 o = *(const float4*)(sOut + row * 36 + q * 4);
            if (write_img) {
                *(float4*)(hout + (size_t)grow * HC + ys * 32 + q * 4) = o;
            } else {
                int gidx = load_idx(batch, grow, g_is64);
                red4(&g_sums[gidx * HC + ys * 32 + q * 4], o);
            }
        }
    }

    // coalesced h-image writeback from sOut (2 kt blocks owned by this CTA)
    if (write_img) {
        int gq = (tid & 31) >> 2;
        int pm = tid & 3;
        int rb2 = tid >> 5;
        int rowA = rb2 * 16 + gq;
        int rowB = rowA + 8;
#pragma unroll
        for (int kb = 0; kb < 2; kb++) {
            int fb = kb * 16;
            float a0v = sOut[rowA * 36 + fb + 2 * pm],     a1v = sOut[rowA * 36 + fb + 2 * pm + 1];
            float b0v = sOut[rowB * 36 + fb + 2 * pm],     b1v = sOut[rowB * 36 + fb + 2 * pm + 1];
            float c0v = sOut[rowA * 36 + fb + 2 * pm + 8], c1v = sOut[rowA * 36 + fb + 2 * pm + 9];
            float d0v = sOut[rowB * 36 + fb + 2 * pm + 8], d1v = sOut[rowB * 36 + fb + 2 * pm + 9];
            uint4 hi4, lo4;
            pack_pair(a0v, a1v, hi4.x, lo4.x);
            pack_pair(b0v, b1v, hi4.y, lo4.y);
            pack_pair(c0v, c1v, hi4.z, lo4.z);
            pack_pair(d0v, d1v, hi4.w, lo4.w);
            size_t base = ((size_t)tile * 8 + ys * 2 + kb) * 1024;
            *(uint4*)(HhiOut + base + tid * 4) = hi4;
            *(uint4*)(HloOut + base + tid * 4) = lo4;
        }
    }
}

// ---------------- output ----------------
__global__ void k_out(const float* __restrict__ Wp, const float* __restrict__ bp,
                      float* __restrict__ out) {
    int g = blockIdx.x;
    int t = threadIdx.x;  // 128
    float c = fmaxf(g_cnt[g], 1.0f);
    float pooled = g_sums[g * HC + t] / c;
    float v = fmaxf(pooled, 0.f) * Wp[t];
    __shared__ float red[4];
#pragma unroll
    for (int o = 16; o > 0; o >>= 1) v += __shfl_down_sync(0xffffffff, v, o);
    if ((t & 31) == 0) red[t >> 5] = v;
    __syncthreads();
    if (t == 0) out[g] = red[0] + red[1] + red[2] + red[3] + bp[0];
}

// ---------------- launch ----------------
extern "C" void kernel_launch(void* const* d_in, const int* in_sizes, int n_in,
                              void* d_out, int out_size) {
    const float* x    = (const float*)d_in[0];
    const void*  ei   = d_in[1];
    const void*  batch= d_in[2];
    const float* W_in = (const float*)d_in[3];
    const float* W_mp = (const float*)d_in[4];
    const float* W_ih = (const float*)d_in[5];
    const float* W_hh = (const float*)d_in[6];
    const float* b_ih = (const float*)d_in[7];
    const float* b_hh = (const float*)d_in[8];
    const float* W_p  = (const float*)d_in[9];
    const float* b_p  = (const float*)d_in[10];
    float* out = (float*)d_out;

    void *hA, *hB, *sumsPtr, *cntPtr, *degPtr, *curPtr;
    void *bHiP, *bLoP, *hHiP, *hLoP;
    cudaGetSymbolAddress(&hA, g_hA);
    cudaGetSymbolAddress(&hB, g_hB);
    cudaGetSymbolAddress(&sumsPtr, g_sums);
    cudaGetSymbolAddress(&cntPtr, g_cnt);
    cudaGetSymbolAddress(&degPtr, g_deg);
    cudaGetSymbolAddress(&curPtr, g_cursor);
    cudaGetSymbolAddress(&bHiP, g_BHi);
    cudaGetSymbolAddress(&bLoP, g_BLo);
    cudaGetSymbolAddress(&hHiP, g_HHi);
    cudaGetSymbolAddress(&hLoP, g_HLo);
    const uint32_t* BHi = (const uint32_t*)bHiP;
    const uint32_t* BLo = (const uint32_t*)bLoP;
    uint32_t* HHi = (uint32_t*)hHiP;  // [2][AIMG_WORDS]
    uint32_t* HLo = (uint32_t*)hLoP;

    cudaFuncSetAttribute(k_gemm, cudaFuncAttributeMaxDynamicSharedMemorySize, SMEM_DYN);

    k_detect<<<1, 256>>>((const int*)ei);

    // pooled-sum scratch + per-graph counts (fused into k_deg)
    cudaMemsetAsync(sumsPtr, 0, (size_t)N_GRAPHSC * HC * sizeof(float), 0);
    cudaMemsetAsync(cntPtr, 0, (size_t)N_GRAPHSC * sizeof(float), 0);

    // CSR build
    cudaMemsetAsync(degPtr, 0, N_NODESC * sizeof(int), 0);
    cudaMemsetAsync(curPtr, 0, N_NODESC * sizeof(int), 0);
    k_deg<<<(N_EDGESC + 255) / 256, 256>>>(ei, batch);
    k_scan1<<<NSCANB, 256>>>();
    k_scan2<<<1, 32>>>();
    k_scan3<<<NSCANB, 256>>>();
    k_fill<<<(N_EDGESC + 255) / 256, 256>>>(ei);

    // weights
    k_prep_wc<<<(STEPSC * H3C * HC + 255) / 256, 256>>>(W_mp, W_ih);
    k_prep_bimg<<<(STEPSC * BIMG_STEP_W + 255) / 256, 256>>>(W_hh);

    // input layer (writes h AND the step-0 h fragment images)
    k_input<<<(N_NODESC + 255) / 256, 256>>>(x, W_in, (float*)hA, HHi, HLo);

    float* hcur = (float*)hA;
    float* hnext = (float*)hB;
    for (int s = 0; s < STEPSC; s++) {
        int pin = s & 1, pout = (s + 1) & 1;
        k_gather<<<N_NODESC / 16, 512>>>(hcur, 0);
        k_gather<<<N_NODESC / 16, 512>>>(hcur, 1);
        dim3 grid(NTILES, 4);
        k_gemm<<<grid, 256, SMEM_DYN>>>(
            hcur, hnext,
            BHi + (size_t)s * BIMG_STEP_W, BLo + (size_t)s * BIMG_STEP_W,
            HHi + (size_t)pin * AIMG_WORDS, HLo + (size_t)pin * AIMG_WORDS,
            HHi + (size_t)pout * AIMG_WORDS, HLo + (size_t)pout * AIMG_WORDS,
            b_ih, b_hh, batch, (s < STEPSC - 1) ? 1 : 0);
        float* tmp = hcur; hcur = hnext; hnext = tmp;
    }
    k_out<<<N_GRAPHSC, 128>>>(W_p, b_p, out);
}

// round 14
// speedup vs baseline: 1.0080x; 1.0080x over previous
#include <cuda_runtime.h>
#include <cstdint>

#define N_NODESC 100000
#define N_EDGESC 1600000
#define N_GRAPHSC 512
#define F_INC 64
#define HC 128
#define H3C 384
#define STEPSC 6
#define NTILES 782                         // ceil(100000/128)
#define AIMG_WORDS ((size_t)NTILES * 8 * 1024)
#define BIMG_KT_W 768                      // 12 n-blocks x 64 words
#define BIMG_STEP_W (4 * 16 * BIMG_KT_W)   // 49152 words per step per image
#define STAGE_W 7168                       // Ahi 2048 | Alo 2048 | Bhi 1536 | Blo 1536
#define HP_W (128 * 36)                    // hprev smem block (stride 36 for banks+16B)
#define SMEM_DYN ((3 * STAGE_W + HP_W) * 4)  // 104448 B
#define NSCANB 98                          // ceil(100000/1024)

// ---------------- device scratch ----------------
__device__ float g_hA[(size_t)N_NODESC * HC];
__device__ float g_hB[(size_t)N_NODESC * HC];
__device__ float g_WcG[(size_t)STEPSC * H3C * HC];
__device__ __align__(16) uint32_t g_AHi[AIMG_WORDS];     // agg fragment image (bf16x2 hi)
__device__ __align__(16) uint32_t g_ALo[AIMG_WORDS];
__device__ __align__(16) uint32_t g_HHi[2][AIMG_WORDS];  // h fragment images, step parity
__device__ __align__(16) uint32_t g_HLo[2][AIMG_WORDS];
__device__ __align__(16) uint32_t g_BHi[(size_t)STEPSC * BIMG_STEP_W];
__device__ __align__(16) uint32_t g_BLo[(size_t)STEPSC * BIMG_STEP_W];
__device__ float g_sums[N_GRAPHSC * HC];
__device__ float g_cnt[N_GRAPHSC];
__device__ int   g_is64;
// CSR
__device__ int g_deg[N_NODESC];
__device__ int g_cursor[N_NODESC];
__device__ int g_rowstart[N_NODESC + 1];
__device__ int g_srcs[N_EDGESC];
__device__ int g_bsum[NSCANB];

// ---------------- helpers ----------------
__device__ __forceinline__ uint32_t smem_u32(const void* p) {
    uint32_t a;
    asm("{ .reg .u64 t; cvta.to.shared.u64 t, %1; cvt.u32.u64 %0, t; }" : "=r"(a) : "l"(p));
    return a;
}
__device__ __forceinline__ uint32_t pack_bf2(float lo, float hi) {
    uint32_t r;
    asm("cvt.rn.bf16x2.f32 %0, %1, %2;" : "=r"(r) : "f"(hi), "f"(lo));
    return r;
}
__device__ __forceinline__ float bf2_low(uint32_t v)  { return __uint_as_float(v << 16); }
__device__ __forceinline__ float bf2_high(uint32_t v) { return __uint_as_float(v & 0xffff0000u); }
__device__ __forceinline__ void pack_pair(float v0, float v1, uint32_t& hi, uint32_t& lo) {
    hi = pack_bf2(v0, v1);
    lo = pack_bf2(v0 - bf2_low(hi), v1 - bf2_high(hi));
}
__device__ __forceinline__ void red4(float* p, float4 v) {
    asm volatile("red.global.add.v4.f32 [%0], {%1,%2,%3,%4};"
                 :: "l"(p), "f"(v.x), "f"(v.y), "f"(v.z), "f"(v.w) : "memory");
}
__device__ __forceinline__ int load_idx(const void* p, long long i, int is64) {
    if (is64) return (int)((const long long*)p)[i];
    return ((const int*)p)[i];
}
__device__ __forceinline__ float sigf(float x) {
    return __fdividef(1.0f, 1.0f + __expf(-x));
}
__device__ __forceinline__ float tanhfast(float x) {
    float e = __expf(2.0f * x);
    return 1.0f - __fdividef(2.0f, e + 1.0f);
}
__device__ __forceinline__ void mma_bf16(float* d, uint32_t a0, uint32_t a1, uint32_t a2,
                                         uint32_t a3, uint32_t b0, uint32_t b1) {
    asm volatile(
        "mma.sync.aligned.m16n8k16.row.col.f32.bf16.bf16.f32 "
        "{%0,%1,%2,%3}, {%4,%5,%6,%7}, {%8,%9}, {%0,%1,%2,%3};"
        : "+f"(d[0]), "+f"(d[1]), "+f"(d[2]), "+f"(d[3])
        : "r"(a0), "r"(a1), "r"(a2), "r"(a3), "r"(b0), "r"(b1));
}
__device__ __forceinline__ void mma3(float* d, const uint4& ah, const uint4& al,
                                     const uint2& bh, const uint2& bl) {
    mma_bf16(d, ah.x, ah.y, ah.z, ah.w, bh.x, bh.y);
    mma_bf16(d, ah.x, ah.y, ah.z, ah.w, bl.x, bl.y);
    mma_bf16(d, al.x, al.y, al.z, al.w, bh.x, bh.y);
}
__device__ __forceinline__ void cpasync16(uint32_t saddr, const void* g) {
    asm volatile("cp.async.cg.shared.global [%0], [%1], 16;" :: "r"(saddr), "l"(g) : "memory");
}
__device__ __forceinline__ void cp_commit() { asm volatile("cp.async.commit_group;" ::: "memory"); }
__device__ __forceinline__ void cp_wait1()  { asm volatile("cp.async.wait_group 1;" ::: "memory"); }
__device__ __forceinline__ void cp_wait0()  { asm volatile("cp.async.wait_group 0;" ::: "memory"); }

// Fragment-image word offset for (row-in-tile rr, pair p) within a 1024-word kt block.
__device__ __forceinline__ int aimg_word(int rr, int p) {
    int g = rr & 7, rh = (rr >> 3) & 1, rb = rr >> 4;
    return rb * 128 + (g * 4 + (p & 3)) * 4 + (p >> 2) * 2 + rh;
}

__device__ __forceinline__ void store_split4(uint32_t* Hi, uint32_t* Lo, size_t base,
                                             int rr, int p0, float4 v) {
    uint32_t h0, l0, h1, l1;
    pack_pair(v.x, v.y, h0, l0);
    pack_pair(v.z, v.w, h1, l1);
    int w0 = aimg_word(rr, p0), w1 = aimg_word(rr, p0 + 1);
    Hi[base + w0] = h0; Hi[base + w1] = h1;
    Lo[base + w0] = l0; Lo[base + w1] = l1;
}

// ---------------- index dtype sniffer ----------------
__global__ void k_detect(const int* __restrict__ ei) {
    int any = 0;
    for (int i = threadIdx.x; i < 2048; i += blockDim.x) any |= ei[2 * i + 1];
    any = __syncthreads_or(any);
    if (threadIdx.x == 0) g_is64 = (any == 0) ? 1 : 0;
}

// ---------------- CSR build (deg + per-graph counts fused) ----------------
__global__ void k_deg(const void* __restrict__ ei, const void* __restrict__ batch) {
    int e = blockIdx.x * blockDim.x + threadIdx.x;
    if (e >= N_EDGESC) return;
    int is64 = g_is64;
    int d = load_idx(ei, (long long)N_EDGESC + e, is64);
    atomicAdd(&g_deg[d], 1);
    if (e < N_NODESC) atomicAdd(&g_cnt[load_idx(batch, e, is64)], 1.0f);
}

__global__ void k_scan1() {
    __shared__ int sred[8];
    int b = blockIdx.x, t = threadIdx.x;
    int i0 = b * 1024 + t * 4;
    int s = 0;
#pragma unroll
    for (int j = 0; j < 4; j++) {
        int i = i0 + j;
        if (i < N_NODESC) s += g_deg[i];
    }
#pragma unroll
    for (int o = 16; o > 0; o >>= 1) s += __shfl_down_sync(0xffffffffu, s, o);
    if ((t & 31) == 0) sred[t >> 5] = s;
    __syncthreads();
    if (t == 0) {
        int tot = 0;
#pragma unroll
        for (int j = 0; j < 8; j++) tot += sred[j];
        g_bsum[b] = tot;
    }
}

__global__ void k_scan2() {
    int lane = threadIdx.x;  // 32
    int base = 0;
    for (int c = 0; c < 4; c++) {
        int i = c * 32 + lane;
        int v = (i < NSCANB) ? g_bsum[i] : 0;
        int s = v;
#pragma unroll
        for (int o = 1; o < 32; o <<= 1) {
            int t = __shfl_up_sync(0xffffffffu, s, o);
            if (lane >= o) s += t;
        }
        if (i < NSCANB) g_bsum[i] = base + (s - v);  // exclusive
        base += __shfl_sync(0xffffffffu, s, 31);
    }
    if (lane == 0) g_rowstart[0] = 0;
}

__global__ void k_scan3() {
    __shared__ int swarp[8];
    int b = blockIdx.x, t = threadIdx.x;
    int i0 = b * 1024 + t * 4;
    int d[4], ts = 0;
#pragma unroll
    for (int j = 0; j < 4; j++) {
        d[j] = (i0 + j < N_NODESC) ? g_deg[i0 + j] : 0;
        ts += d[j];
    }
    int s = ts;
#pragma unroll
    for (int o = 1; o < 32; o <<= 1) {
        int v = __shfl_up_sync(0xffffffffu, s, o);
        if ((t & 31) >= o) s += v;
    }
    if ((t & 31) == 31) swarp[t >> 5] = s;
    __syncthreads();
    int wpre = 0;
    for (int j = 0; j < (t >> 5); j++) wpre += swarp[j];
    int run = g_bsum[b] + wpre + (s - ts);
#pragma unroll
    for (int j = 0; j < 4; j++) {
        run += d[j];
        if (i0 + j < N_NODESC) g_rowstart[i0 + j + 1] = run;
    }
}

__global__ void k_fill(const void* __restrict__ ei) {
    int e = blockIdx.x * blockDim.x + threadIdx.x;
    if (e >= N_EDGESC) return;
    int is64 = g_is64;
    int s = load_idx(ei, e, is64);
    int d = load_idx(ei, (long long)N_EDGESC + e, is64);
    int pos = g_rowstart[d] + atomicAdd(&g_cursor[d], 1);
    g_srcs[pos] = s;
}

// ---------------- gather: agg[n] = sum h[src]; smem-staged coalesced image writes ----------------
// Full-width (R12-validated), unroll 8 for MLP.
__global__ void __launch_bounds__(512) k_gather(const float* __restrict__ h) {
    __shared__ uint32_t stg[2048];  // hi [0,1024) | lo [1024,2048)
    int w = threadIdx.x >> 5, lane = threadIdx.x & 31;
    int n = blockIdx.x * 16 + w;    // always < N_NODESC (100000 = 6250*16)
    int beg = g_rowstart[n], end = g_rowstart[n + 1];
    const float4* hb = (const float4*)h;
    float4 a0 = make_float4(0.f, 0.f, 0.f, 0.f);
    float4 a1 = make_float4(0.f, 0.f, 0.f, 0.f);
    float4 a2 = make_float4(0.f, 0.f, 0.f, 0.f);
    float4 a3 = make_float4(0.f, 0.f, 0.f, 0.f);
    int i = beg;
    for (; i + 8 <= end; i += 8) {
        int s0 = __ldg(&g_srcs[i]);
        int s1 = __ldg(&g_srcs[i + 1]);
        int s2 = __ldg(&g_srcs[i + 2]);
        int s3 = __ldg(&g_srcs[i + 3]);
        int s4 = __ldg(&g_srcs[i + 4]);
        int s5 = __ldg(&g_srcs[i + 5]);
        int s6 = __ldg(&g_srcs[i + 6]);
        int s7 = __ldg(&g_srcs[i + 7]);
        float4 v0 = hb[(size_t)s0 * 32 + lane];
        float4 v1 = hb[(size_t)s1 * 32 + lane];
        float4 v2 = hb[(size_t)s2 * 32 + lane];
        float4 v3 = hb[(size_t)s3 * 32 + lane];
        float4 v4 = hb[(size_t)s4 * 32 + lane];
        float4 v5 = hb[(size_t)s5 * 32 + lane];
        float4 v6 = hb[(size_t)s6 * 32 + lane];
        float4 v7 = hb[(size_t)s7 * 32 + lane];
        a0.x += v0.x; a0.y += v0.y; a0.z += v0.z; a0.w += v0.w;
        a1.x += v1.x; a1.y += v1.y; a1.z += v1.z; a1.w += v1.w;
        a2.x += v2.x; a2.y += v2.y; a2.z += v2.z; a2.w += v2.w;
        a3.x += v3.x; a3.y += v3.y; a3.z += v3.z; a3.w += v3.w;
        a0.x += v4.x; a0.y += v4.y; a0.z += v4.z; a0.w += v4.w;
        a1.x += v5.x; a1.y += v5.y; a1.z += v5.z; a1.w += v5.w;
        a2.x += v6.x; a2.y += v6.y; a2.z += v6.z; a2.w += v6.w;
        a3.x += v7.x; a3.y += v7.y; a3.z += v7.z; a3.w += v7.w;
    }
    for (; i + 2 <= end; i += 2) {
        int s0 = __ldg(&g_srcs[i]);
        int s1 = __ldg(&g_srcs[i + 1]);
        float4 v0 = hb[(size_t)s0 * 32 + lane];
        float4 v1 = hb[(size_t)s1 * 32 + lane];
        a0.x += v0.x; a0.y += v0.y; a0.z += v0.z; a0.w += v0.w;
        a1.x += v1.x; a1.y += v1.y; a1.z += v1.z; a1.w += v1.w;
    }
    if (i < end) {
        int s0 = __ldg(&g_srcs[i]);
        float4 v0 = hb[(size_t)s0 * 32 + lane];
        a0.x += v0.x; a0.y += v0.y; a0.z += v0.z; a0.w += v0.w;
    }
    a0.x += a1.x; a0.y += a1.y; a0.z += a1.z; a0.w += a1.w;
    a2.x += a3.x; a2.y += a3.y; a2.z += a3.z; a2.w += a3.w;
    a0.x += a2.x; a0.y += a2.y; a0.z += a2.z; a0.w += a2.w;

    {
        int g = w & 7, rh = (w >> 3) & 1;
        int kt = lane >> 2, p0 = (lane & 3) * 2;
        uint32_t h0, l0, h1, l1;
        pack_pair(a0.x, a0.y, h0, l0);
        pack_pair(a0.z, a0.w, h1, l1);
        int w0 = (g * 4 + (p0 & 3)) * 4 + ((p0 >> 2) << 1) + rh;
        int p1 = p0 + 1;
        int w1 = (g * 4 + (p1 & 3)) * 4 + ((p1 >> 2) << 1) + rh;
        stg[kt * 128 + w0] = h0;
        stg[kt * 128 + w1] = h1;
        stg[1024 + kt * 128 + w0] = l0;
        stg[1024 + kt * 128 + w1] = l1;
    }
    __syncthreads();

    int tile = blockIdx.x >> 3;
    int rb = blockIdx.x & 7;
    int t = threadIdx.x;
    int q = t & 255, kt2 = q >> 5, w4 = q & 31;
    const uint4* src = (const uint4*)(stg + ((t < 256) ? 0 : 1024));
    uint32_t* dst = (t < 256) ? g_AHi : g_ALo;
    *(uint4*)(dst + ((size_t)tile * 8 + kt2) * 1024 + rb * 128 + w4 * 4) = src[q];
}

// ---------------- weight precompute ----------------
__global__ void k_prep_wc(const float* __restrict__ Wmp, const float* __restrict__ Wih) {
    int idx = blockIdx.x * blockDim.x + threadIdx.x;
    if (idx >= STEPSC * H3C * HC) return;
    int k = idx % HC;
    int j = (idx / HC) % H3C;
    int s = idx / (HC * H3C);
    const float4* wm = (const float4*)(Wmp + ((size_t)s * HC + k) * HC);
    const float4* wi = (const float4*)(Wih + (size_t)j * HC);
    float acc = 0.f;
#pragma unroll
    for (int m = 0; m < HC / 4; m++) {
        float4 a = wm[m], b = wi[m];
        acc += a.x * b.x + a.y * b.y + a.z * b.z + a.w * b.w;
    }
    g_WcG[idx] = acc;
}

// B fragment images (phase-split): [s][ys][kt][nb' 0..11][lane][j].
__global__ void k_prep_bimg(const float* __restrict__ Whh) {
    int idx = blockIdx.x * blockDim.x + threadIdx.x;
    if (idx >= STEPSC * BIMG_STEP_W) return;
    int j = idx & 1;
    int lane = (idx >> 1) & 31;
    int t = idx >> 6;
    int nbp = t % 12; t /= 12;
    int kt = t % 16;  t /= 16;
    int ys = t % 4;
    int s = t / 4;
    int g = lane >> 2, tI = lane & 3;
    int k0 = kt * 16 + 2 * tI + 8 * j;
    float v[2];
#pragma unroll
    for (int e = 0; e < 2; e++) {
        int k = k0 + e;
        float val;
        if (nbp < 8) {
            int c = nbp * 8 + g;
            int f = ys * 32 + (c >> 1);
            int gate = c & 1;
            val = (k < HC) ? g_WcG[((size_t)s * H3C + gate * HC + f) * HC + k]
                           : Whh[(size_t)(gate * HC + f) * HC + (k - HC)];
        } else {
            int f = ys * 32 + (nbp - 8) * 8 + g;
            val = (k < HC) ? g_WcG[((size_t)s * H3C + 2 * HC + f) * HC + k]
                           : Whh[(size_t)(2 * HC + f) * HC + (k - HC)];
        }
        v[e] = val;
    }
    uint32_t hi, lo;
    pack_pair(v[0], v[1], hi, lo);
    g_BHi[idx] = hi;
    g_BLo[idx] = lo;
}

// ---------------- input layer: h = tanh(x @ W_in), fused fragment-image writes ----------------
__global__ void __launch_bounds__(256) k_input(
    const float* __restrict__ x, const float* __restrict__ Win, float* __restrict__ h,
    uint32_t* __restrict__ Hi, uint32_t* __restrict__ Lo)
{
    __shared__ float sw[F_INC * HC];  // [k][c], 32KB
    int tid = threadIdx.x;
    for (int i = tid; i < F_INC * HC; i += 256) sw[i] = Win[i];
    __syncthreads();
    int n = blockIdx.x * 256 + tid;
    if (n >= N_NODESC) return;

    float4 xr[16];
    const float4* xp = (const float4*)(x + (size_t)n * F_INC);
#pragma unroll
    for (int j = 0; j < 16; j++) xr[j] = xp[j];

    int tile = n >> 7, rr = n & 127;
    float* hrow = h + (size_t)n * HC;

#pragma unroll 1
    for (int cg = 0; cg < 8; cg++) {
        float acc[16];
#pragma unroll
        for (int j = 0; j < 16; j++) acc[j] = 0.f;
#pragma unroll
        for (int k4 = 0; k4 < 16; k4++) {
            float4 xv4 = xr[k4];
            float xs[4] = {xv4.x, xv4.y, xv4.z, xv4.w};
#pragma unroll
            for (int kk = 0; kk < 4; kk++) {
                int k = k4 * 4 + kk;
                const float4* wp = (const float4*)(sw + k * HC + cg * 16);
#pragma unroll
                for (int j4 = 0; j4 < 4; j4++) {
                    float4 w = wp[j4];
                    acc[j4 * 4 + 0] += xs[kk] * w.x;
                    acc[j4 * 4 + 1] += xs[kk] * w.y;
                    acc[j4 * 4 + 2] += xs[kk] * w.z;
                    acc[j4 * 4 + 3] += xs[kk] * w.w;
                }
            }
        }
        size_t base = ((size_t)tile * 8 + cg) * 1024;
#pragma unroll
        for (int j = 0; j < 4; j++) {
            float4 o;
            o.x = tanhf(acc[j * 4 + 0]);
            o.y = tanhf(acc[j * 4 + 1]);
            o.z = tanhf(acc[j * 4 + 2]);
            o.w = tanhf(acc[j * 4 + 3]);
            *(float4*)(hrow + cg * 16 + j * 4) = o;
            store_split4(Hi, Lo, base, rr, j * 2, o);
        }
    }
}

// ---------------- bf16x3 mma.sync fused GEMM + GRU, phase-split columns ----------------
// hprev staged via cp.async into smem (appended to chunk 0's group).
__global__ void __launch_bounds__(256, 2) k_gemm(
    const float* __restrict__ hin, float* __restrict__ hout,
    const uint32_t* __restrict__ Bhi, const uint32_t* __restrict__ Blo,
    const uint32_t* __restrict__ HhiIn, const uint32_t* __restrict__ HloIn,
    uint32_t* __restrict__ HhiOut, uint32_t* __restrict__ HloOut,
    const float* __restrict__ bih, const float* __restrict__ bhh,
    const void* __restrict__ batch, int write_img)
{
    extern __shared__ uint32_t smu[];  // 3 stages x STAGE_W | hp [128][36] floats
    __shared__ float sbias[4][32];

    const int tid = threadIdx.x;
    const int lane = tid & 31;
    const int warp = tid >> 5;
    const int warpM = warp & 1;
    const int warpN = warp >> 1;
    const int tile = blockIdx.x;
    const int row0 = tile * 128;
    const int ys = blockIdx.y;
    float* sHp = (float*)(smu + 3 * STAGE_W);

    if (tid < 32) {
        int f = ys * 32 + tid;
        sbias[0][tid] = bih[f] + bhh[f];
        sbias[1][tid] = bih[HC + f] + bhh[HC + f];
        sbias[2][tid] = bih[2 * HC + f];
        sbias[3][tid] = bhh[2 * HC + f];
    }

    const uint32_t* Bh = Bhi + (size_t)ys * 16 * BIMG_KT_W;
    const uint32_t* Bl = Blo + (size_t)ys * 16 * BIMG_KT_W;
    const uint32_t smem_base = smem_u32(smu);
    const uint32_t hp_base = smem_base + (3 * STAGE_W) * 4;

    auto issue = [&](int c) {
        uint32_t d = smem_base + ((c % 3) * STAGE_W) * 4;
#pragma unroll
        for (int kk = 0; kk < 2; kk++) {
            int kt = 2 * c + kk;
            const uint32_t *ah, *al;
            if (kt < 8) {
                ah = g_AHi + ((size_t)tile * 8 + kt) * 1024;
                al = g_ALo + ((size_t)tile * 8 + kt) * 1024;
            } else {
                ah = HhiIn + ((size_t)tile * 8 + (kt - 8)) * 1024;
                al = HloIn + ((size_t)tile * 8 + (kt - 8)) * 1024;
            }
            cpasync16(d + kk * 4096 + tid * 16,        ah + tid * 4);
            cpasync16(d + 8192 + kk * 4096 + tid * 16, al + tid * 4);
            if (tid < 192) {
                cpasync16(d + 16384 + kk * 3072 + tid * 16, Bh + (size_t)kt * BIMG_KT_W + tid * 4);
                cpasync16(d + 22528 + kk * 3072 + tid * 16, Bl + (size_t)kt * BIMG_KT_W + tid * 4);
            }
        }
        if (c == 0) {
            // hprev block: 128 rows x 32 floats, padded stride 36 (16B-aligned rows)
#pragma unroll
            for (int rep = 0; rep < 4; rep++) {
                int idx = tid + rep * 256;       // 0..1023
                int row = idx >> 3, ch = idx & 7;
                int grow = row0 + row;
                if (grow >= N_NODESC) grow = N_NODESC - 1;  // clamp: finite, row-local
                cpasync16(hp_base + (row * 36 + ch * 4) * 4,
                          hin + (size_t)grow * HC + ys * 32 + ch * 4);
            }
        }
        cp_commit();
    };

    float acc_rz0[4][4], acc_rz1[4][4], acc_in[4][4], acc_hn[4][4];
#pragma unroll
    for (int mt = 0; mt < 4; mt++)
#pragma unroll
        for (int r = 0; r < 4; r++) {
            acc_rz0[mt][r] = 0.f; acc_rz1[mt][r] = 0.f;
            acc_in[mt][r] = 0.f;  acc_hn[mt][r] = 0.f;
        }

    issue(0);
    issue(1);

    for (int c = 0; c < 8; c++) {
        if (c < 7) cp_wait1();
        else cp_wait0();
        __syncthreads();
        if (c <= 5) issue(c + 2);

        const uint32_t* st = smu + (c % 3) * STAGE_W;
        bool ph0 = (c < 4);
#pragma unroll
        for (int kk = 0; kk < 2; kk++) {
            const uint32_t* Ahw = st + kk * 1024;
            const uint32_t* Alw = st + 2048 + kk * 1024;
            const uint32_t* Bhw = st + 4096 + kk * BIMG_KT_W;
            const uint32_t* Blw = st + 5632 + kk * BIMG_KT_W;

            uint2 rz0h = *(const uint2*)(Bhw + (2 * warpN) * 64 + lane * 2);
            uint2 rz0l = *(const uint2*)(Blw + (2 * warpN) * 64 + lane * 2);
            uint2 rz1h = *(const uint2*)(Bhw + (2 * warpN + 1) * 64 + lane * 2);
            uint2 rz1l = *(const uint2*)(Blw + (2 * warpN + 1) * 64 + lane * 2);
            uint2 xh   = *(const uint2*)(Bhw + (8 + warpN) * 64 + lane * 2);
            uint2 xl   = *(const uint2*)(Blw + (8 + warpN) * 64 + lane * 2);
#pragma unroll
            for (int mt = 0; mt < 4; mt++) {
                int rb = warpM * 4 + mt;
                uint4 ah = *(const uint4*)(Ahw + rb * 128 + lane * 4);
                uint4 al = *(const uint4*)(Alw + rb * 128 + lane * 4);
                mma3(acc_rz0[mt], ah, al, rz0h, rz0l);
                mma3(acc_rz1[mt], ah, al, rz1h, rz1l);
                if (ph0) mma3(acc_in[mt], ah, al, xh, xl);
                else     mma3(acc_hn[mt], ah, al, xh, xl);
            }
        }
    }
    __syncthreads();   // all compute done before sOut aliases pipeline smem

    // ---------------- fused GRU epilogue (phase-split layout) ----------------
    float* sOut = (float*)smu;  // [128][36], aliases stage smem (hp block untouched)
    const int g = lane >> 2;
    const int tI = lane & 3;
    const bool use1 = (tI >= 2);

#pragma unroll
    for (int mt = 0; mt < 4; mt++) {
        int rowl = warpM * 64 + mt * 16 + g;
#pragma unroll
        for (int e = 0; e < 2; e++) {
            int u = 2 * tI + e;
            int src = g * 4 + (u & 3);
            float v0[4], v1[4];
#pragma unroll
            for (int i = 0; i < 4; i++) {
                v0[i] = __shfl_sync(0xffffffffu, acc_rz0[mt][i], src);
                v1[i] = __shfl_sync(0xffffffffu, acc_rz1[mt][i], src);
            }
            float Sr_a = use1 ? v1[0] : v0[0];
            float Sz_a = use1 ? v1[1] : v0[1];
            float Sr_b = use1 ? v1[2] : v0[2];
            float Sz_b = use1 ? v1[3] : v0[3];
            float in_a = acc_in[mt][e],     in_b = acc_in[mt][2 + e];
            float hn_a = acc_hn[mt][e],     hn_b = acc_hn[mt][2 + e];
            int fl = warpN * 8 + u;
            float hpa = sHp[rowl * 36 + fl];
            float hpb = sHp[(rowl + 8) * 36 + fl];
            float ra = sigf(Sr_a + sbias[0][fl]);
            float za = sigf(Sz_a + sbias[1][fl]);
            float na = tanhfast(in_a + sbias[2][fl] + ra * (hn_a + sbias[3][fl]));
            float rb2 = sigf(Sr_b + sbias[0][fl]);
            float zb = sigf(Sz_b + sbias[1][fl]);
            float nb2 = tanhfast(in_b + sbias[2][fl] + rb2 * (hn_b + sbias[3][fl]));
            sOut[rowl * 36 + fl]       = (1.f - za) * na + za * hpa;
            sOut[(rowl + 8) * 36 + fl] = (1.f - zb) * nb2 + zb * hpb;
        }
    }
    __syncthreads();

    // hout (fp32) writeback / pool accumulation
#pragma unroll
    for (int rep = 0; rep < 4; rep++) {
        int idx = tid + rep * 256;
        int row = idx >> 3, q = idx & 7;
        int grow = row0 + row;
        if (grow < N_NODESC) {
            float4 o = *(const float4*)(sOut + row * 36 + q * 4);
            if (write_img) {
                *(float4*)(hout + (size_t)grow * HC + ys * 32 + q * 4) = o;
            } else {
                int gidx = load_idx(batch, grow, g_is64);
                red4(&g_sums[gidx * HC + ys * 32 + q * 4], o);
            }
        }
    }

    // coalesced h-image writeback from sOut (2 kt blocks owned by this CTA)
    if (write_img) {
        int gq = (tid & 31) >> 2;
        int pm = tid & 3;
        int rb2 = tid >> 5;
        int rowA = rb2 * 16 + gq;
        int rowB = rowA + 8;
#pragma unroll
        for (int kb = 0; kb < 2; kb++) {
            int fb = kb * 16;
            float a0v = sOut[rowA * 36 + fb + 2 * pm],     a1v = sOut[rowA * 36 + fb + 2 * pm + 1];
            float b0v = sOut[rowB * 36 + fb + 2 * pm],     b1v = sOut[rowB * 36 + fb + 2 * pm + 1];
            float c0v = sOut[rowA * 36 + fb + 2 * pm + 8], c1v = sOut[rowA * 36 + fb + 2 * pm + 9];
            float d0v = sOut[rowB * 36 + fb + 2 * pm + 8], d1v = sOut[rowB * 36 + fb + 2 * pm + 9];
            uint4 hi4, lo4;
            pack_pair(a0v, a1v, hi4.x, lo4.x);
            pack_pair(b0v, b1v, hi4.y, lo4.y);
            pack_pair(c0v, c1v, hi4.z, lo4.z);
            pack_pair(d0v, d1v, hi4.w, lo4.w);
            size_t base = ((size_t)tile * 8 + ys * 2 + kb) * 1024;
            *(uint4*)(HhiOut + base + tid * 4) = hi4;
            *(uint4*)(HloOut + base + tid * 4) = lo4;
        }
    }
}

// ---------------- output ----------------
__global__ void k_out(const float* __restrict__ Wp, const float* __restrict__ bp,
                      float* __restrict__ out) {
    int g = blockIdx.x;
    int t = threadIdx.x;  // 128
    float c = fmaxf(g_cnt[g], 1.0f);
    float pooled = g_sums[g * HC + t] / c;
    float v = fmaxf(pooled, 0.f) * Wp[t];
    __shared__ float red[4];
#pragma unroll
    for (int o = 16; o > 0; o >>= 1) v += __shfl_down_sync(0xffffffff, v, o);
    if ((t & 31) == 0) red[t >> 5] = v;
    __syncthreads();
    if (t == 0) out[g] = red[0] + red[1] + red[2] + red[3] + bp[0];
}

// ---------------- launch ----------------
extern "C" void kernel_launch(void* const* d_in, const int* in_sizes, int n_in,
                              void* d_out, int out_size) {
    const float* x    = (const float*)d_in[0];
    const void*  ei   = d_in[1];
    const void*  batch= d_in[2];
    const float* W_in = (const float*)d_in[3];
    const float* W_mp = (const float*)d_in[4];
    const float* W_ih = (const float*)d_in[5];
    const float* W_hh = (const float*)d_in[6];
    const float* b_ih = (const float*)d_in[7];
    const float* b_hh = (const float*)d_in[8];
    const float* W_p  = (const float*)d_in[9];
    const float* b_p  = (const float*)d_in[10];
    float* out = (float*)d_out;

    void *hA, *hB, *sumsPtr, *cntPtr, *degPtr, *curPtr;
    void *bHiP, *bLoP, *hHiP, *hLoP;
    cudaGetSymbolAddress(&hA, g_hA);
    cudaGetSymbolAddress(&hB, g_hB);
    cudaGetSymbolAddress(&sumsPtr, g_sums);
    cudaGetSymbolAddress(&cntPtr, g_cnt);
    cudaGetSymbolAddress(&degPtr, g_deg);
    cudaGetSymbolAddress(&curPtr, g_cursor);
    cudaGetSymbolAddress(&bHiP, g_BHi);
    cudaGetSymbolAddress(&bLoP, g_BLo);
    cudaGetSymbolAddress(&hHiP, g_HHi);
    cudaGetSymbolAddress(&hLoP, g_HLo);
    const uint32_t* BHi = (const uint32_t*)bHiP;
    const uint32_t* BLo = (const uint32_t*)bLoP;
    uint32_t* HHi = (uint32_t*)hHiP;  // [2][AIMG_WORDS]
    uint32_t* HLo = (uint32_t*)hLoP;

    cudaFuncSetAttribute(k_gemm, cudaFuncAttributeMaxDynamicSharedMemorySize, SMEM_DYN);

    k_detect<<<1, 256>>>((const int*)ei);

    // pooled-sum scratch + per-graph counts (fused into k_deg)
    cudaMemsetAsync(sumsPtr, 0, (size_t)N_GRAPHSC * HC * sizeof(float), 0);
    cudaMemsetAsync(cntPtr, 0, (size_t)N_GRAPHSC * sizeof(float), 0);

    // CSR build
    cudaMemsetAsync(degPtr, 0, N_NODESC * sizeof(int), 0);
    cudaMemsetAsync(curPtr, 0, N_NODESC * sizeof(int), 0);
    k_deg<<<(N_EDGESC + 255) / 256, 256>>>(ei, batch);
    k_scan1<<<NSCANB, 256>>>();
    k_scan2<<<1, 32>>>();
    k_scan3<<<NSCANB, 256>>>();
    k_fill<<<(N_EDGESC + 255) / 256, 256>>>(ei);

    // weights
    k_prep_wc<<<(STEPSC * H3C * HC + 255) / 256, 256>>>(W_mp, W_ih);
    k_prep_bimg<<<(STEPSC * BIMG_STEP_W + 255) / 256, 256>>>(W_hh);

    // input layer (writes h AND the step-0 h fragment images)
    k_input<<<(N_NODESC + 255) / 256, 256>>>(x, W_in, (float*)hA, HHi, HLo);

    float* hcur = (float*)hA;
    float* hnext = (float*)hB;
    for (int s = 0; s < STEPSC; s++) {
        int pin = s & 1, pout = (s + 1) & 1;
        k_gather<<<N_NODESC / 16, 512>>>(hcur);
        dim3 grid(NTILES, 4);
        k_gemm<<<grid, 256, SMEM_DYN>>>(
            hcur, hnext,
            BHi + (size_t)s * BIMG_STEP_W, BLo + (size_t)s * BIMG_STEP_W,
            HHi + (size_t)pin * AIMG_WORDS, HLo + (size_t)pin * AIMG_WORDS,
            HHi + (size_t)pout * AIMG_WORDS, HLo + (size_t)pout * AIMG_WORDS,
            b_ih, b_hh, batch, (s < STEPSC - 1) ? 1 : 0);
        float* tmp = hcur; hcur = hnext; hnext = tmp;
    }
    k_out<<<N_GRAPHSC, 128>>>(W_p, b_p, out);
}

// round 15
// speedup vs baseline: 1.1128x; 1.1040x over previous
#include <cuda_runtime.h>
#include <cstdint>

#define N_NODESC 100000
#define N_EDGESC 1600000
#define N_GRAPHSC 512
#define F_INC 64
#define HC 128
#define H3C 384
#define STEPSC 6
#define NTILES 782                         // ceil(100000/128)
#define AIMG_WORDS ((size_t)NTILES * 8 * 1024)
#define BIMG_KT_W 768                      // 12 n-blocks x 64 words
#define BIMG_STEP_W (4 * 16 * BIMG_KT_W)   // 49152 words per step per image
#define STAGE_W 7168                       // Ahi 2048 | Alo 2048 | Bhi 1536 | Blo 1536
#define HP_W (128 * 36)                    // hprev smem block (stride 36: conflict-free, 16B rows)
#define SMEM_DYN ((3 * STAGE_W + HP_W) * 4)  // 104448 B
#define NSCANB 98                          // ceil(100000/1024)

// ---------------- device scratch ----------------
__device__ float g_hA[(size_t)N_NODESC * HC];
__device__ float g_hB[(size_t)N_NODESC * HC];
__device__ float g_WcG[(size_t)STEPSC * H3C * HC];
__device__ __align__(16) uint32_t g_AHi[AIMG_WORDS];     // agg fragment image (bf16x2 hi)
__device__ __align__(16) uint32_t g_ALo[AIMG_WORDS];
__device__ __align__(16) uint32_t g_HHi[2][AIMG_WORDS];  // h fragment images, step parity
__device__ __align__(16) uint32_t g_HLo[2][AIMG_WORDS];
__device__ __align__(16) uint32_t g_BHi[(size_t)STEPSC * BIMG_STEP_W];
__device__ __align__(16) uint32_t g_BLo[(size_t)STEPSC * BIMG_STEP_W];
__device__ float g_sums[N_GRAPHSC * HC];
__device__ float g_cnt[N_GRAPHSC];
__device__ int   g_is64;
// CSR
__device__ int g_deg[N_NODESC];
__device__ int g_cursor[N_NODESC];
__device__ int g_rowstart[N_NODESC + 1];
__device__ int g_srcs[N_EDGESC];
__device__ int g_bsum[NSCANB];

// ---------------- helpers ----------------
__device__ __forceinline__ uint32_t smem_u32(const void* p) {
    uint32_t a;
    asm("{ .reg .u64 t; cvta.to.shared.u64 t, %1; cvt.u32.u64 %0, t; }" : "=r"(a) : "l"(p));
    return a;
}
__device__ __forceinline__ uint32_t pack_bf2(float lo, float hi) {
    uint32_t r;
    asm("cvt.rn.bf16x2.f32 %0, %1, %2;" : "=r"(r) : "f"(hi), "f"(lo));
    return r;
}
__device__ __forceinline__ float bf2_low(uint32_t v)  { return __uint_as_float(v << 16); }
__device__ __forceinline__ float bf2_high(uint32_t v) { return __uint_as_float(v & 0xffff0000u); }
__device__ __forceinline__ void pack_pair(float v0, float v1, uint32_t& hi, uint32_t& lo) {
    hi = pack_bf2(v0, v1);
    lo = pack_bf2(v0 - bf2_low(hi), v1 - bf2_high(hi));
}
__device__ __forceinline__ void red4(float* p, float4 v) {
    asm volatile("red.global.add.v4.f32 [%0], {%1,%2,%3,%4};"
                 :: "l"(p), "f"(v.x), "f"(v.y), "f"(v.z), "f"(v.w) : "memory");
}
__device__ __forceinline__ int load_idx(const void* p, long long i, int is64) {
    if (is64) return (int)((const long long*)p)[i];
    return ((const int*)p)[i];
}
__device__ __forceinline__ float sigf(float x) {
    return __fdividef(1.0f, 1.0f + __expf(-x));
}
__device__ __forceinline__ float tanhfast(float x) {
    float e = __expf(2.0f * x);
    return 1.0f - __fdividef(2.0f, e + 1.0f);
}
__device__ __forceinline__ void mma_bf16(float* d, uint32_t a0, uint32_t a1, uint32_t a2,
                                         uint32_t a3, uint32_t b0, uint32_t b1) {
    asm volatile(
        "mma.sync.aligned.m16n8k16.row.col.f32.bf16.bf16.f32 "
        "{%0,%1,%2,%3}, {%4,%5,%6,%7}, {%8,%9}, {%0,%1,%2,%3};"
        : "+f"(d[0]), "+f"(d[1]), "+f"(d[2]), "+f"(d[3])
        : "r"(a0), "r"(a1), "r"(a2), "r"(a3), "r"(b0), "r"(b1));
}
__device__ __forceinline__ void mma3(float* d, const uint4& ah, const uint4& al,
                                     const uint2& bh, const uint2& bl) {
    mma_bf16(d, ah.x, ah.y, ah.z, ah.w, bh.x, bh.y);
    mma_bf16(d, ah.x, ah.y, ah.z, ah.w, bl.x, bl.y);
    mma_bf16(d, al.x, al.y, al.z, al.w, bh.x, bh.y);
}
__device__ __forceinline__ void cpasync16(uint32_t saddr, const void* g) {
    asm volatile("cp.async.cg.shared.global [%0], [%1], 16;" :: "r"(saddr), "l"(g) : "memory");
}
__device__ __forceinline__ void cp_commit() { asm volatile("cp.async.commit_group;" ::: "memory"); }
__device__ __forceinline__ void cp_wait1()  { asm volatile("cp.async.wait_group 1;" ::: "memory"); }
__device__ __forceinline__ void cp_wait0()  { asm volatile("cp.async.wait_group 0;" ::: "memory"); }

// Fragment-image word offset for (row-in-tile rr, pair p) within a 1024-word kt block.
__device__ __forceinline__ int aimg_word(int rr, int p) {
    int g = rr & 7, rh = (rr >> 3) & 1, rb = rr >> 4;
    return rb * 128 + (g * 4 + (p & 3)) * 4 + (p >> 2) * 2 + rh;
}

__device__ __forceinline__ void store_split4(uint32_t* Hi, uint32_t* Lo, size_t base,
                                             int rr, int p0, float4 v) {
    uint32_t h0, l0, h1, l1;
    pack_pair(v.x, v.y, h0, l0);
    pack_pair(v.z, v.w, h1, l1);
    int w0 = aimg_word(rr, p0), w1 = aimg_word(rr, p0 + 1);
    Hi[base + w0] = h0; Hi[base + w1] = h1;
    Lo[base + w0] = l0; Lo[base + w1] = l1;
}

// ---------------- index dtype sniffer ----------------
__global__ void k_detect(const int* __restrict__ ei) {
    int any = 0;
    for (int i = threadIdx.x; i < 2048; i += blockDim.x) any |= ei[2 * i + 1];
    any = __syncthreads_or(any);
    if (threadIdx.x == 0) g_is64 = (any == 0) ? 1 : 0;
}

// ---------------- CSR build ----------------
__global__ void k_deg(const void* __restrict__ ei) {
    int e = blockIdx.x * blockDim.x + threadIdx.x;
    if (e >= N_EDGESC) return;
    int d = load_idx(ei, (long long)N_EDGESC + e, g_is64);
    atomicAdd(&g_deg[d], 1);
}

__global__ void k_scan1() {
    __shared__ int sred[8];
    int b = blockIdx.x, t = threadIdx.x;
    int i0 = b * 1024 + t * 4;
    int s = 0;
#pragma unroll
    for (int j = 0; j < 4; j++) {
        int i = i0 + j;
        if (i < N_NODESC) s += g_deg[i];
    }
#pragma unroll
    for (int o = 16; o > 0; o >>= 1) s += __shfl_down_sync(0xffffffffu, s, o);
    if ((t & 31) == 0) sred[t >> 5] = s;
    __syncthreads();
    if (t == 0) {
        int tot = 0;
#pragma unroll
        for (int j = 0; j < 8; j++) tot += sred[j];
        g_bsum[b] = tot;
    }
}

__global__ void k_scan2() {
    int lane = threadIdx.x;  // 32
    int base = 0;
    for (int c = 0; c < 4; c++) {
        int i = c * 32 + lane;
        int v = (i < NSCANB) ? g_bsum[i] : 0;
        int s = v;
#pragma unroll
        for (int o = 1; o < 32; o <<= 1) {
            int t = __shfl_up_sync(0xffffffffu, s, o);
            if (lane >= o) s += t;
        }
        if (i < NSCANB) g_bsum[i] = base + (s - v);  // exclusive
        base += __shfl_sync(0xffffffffu, s, 31);
    }
    if (lane == 0) g_rowstart[0] = 0;
}

__global__ void k_scan3() {
    __shared__ int swarp[8];
    int b = blockIdx.x, t = threadIdx.x;
    int i0 = b * 1024 + t * 4;
    int d[4], ts = 0;
#pragma unroll
    for (int j = 0; j < 4; j++) {
        d[j] = (i0 + j < N_NODESC) ? g_deg[i0 + j] : 0;
        ts += d[j];
    }
    int s = ts;
#pragma unroll
    for (int o = 1; o < 32; o <<= 1) {
        int v = __shfl_up_sync(0xffffffffu, s, o);
        if ((t & 31) >= o) s += v;
    }
    if ((t & 31) == 31) swarp[t >> 5] = s;
    __syncthreads();
    int wpre = 0;
    for (int j = 0; j < (t >> 5); j++) wpre += swarp[j];
    int run = g_bsum[b] + wpre + (s - ts);
#pragma unroll
    for (int j = 0; j < 4; j++) {
        run += d[j];
        if (i0 + j < N_NODESC) g_rowstart[i0 + j + 1] = run;
    }
}

__global__ void k_fill(const void* __restrict__ ei) {
    int e = blockIdx.x * blockDim.x + threadIdx.x;
    if (e >= N_EDGESC) return;
    int is64 = g_is64;
    int s = load_idx(ei, e, is64);
    int d = load_idx(ei, (long long)N_EDGESC + e, is64);
    int pos = g_rowstart[d] + atomicAdd(&g_cursor[d], 1);
    g_srcs[pos] = s;
}

// ---------------- graph node counts (launch-invariant) ----------------
__global__ void k_cnt(const void* __restrict__ batch) {
    int i = blockIdx.x * blockDim.x + threadIdx.x;
    if (i >= N_NODESC) return;
    atomicAdd(&g_cnt[load_idx(batch, i, g_is64)], 1.0f);
}

// ---------------- gather: agg[n] = sum h[src]; smem-staged coalesced image writes ----------------
// Exact R12-validated form (unroll 4).
__global__ void __launch_bounds__(512) k_gather(const float* __restrict__ h) {
    __shared__ uint32_t stg[2048];  // hi [0,1024) | lo [1024,2048)
    int w = threadIdx.x >> 5, lane = threadIdx.x & 31;
    int n = blockIdx.x * 16 + w;    // always < N_NODESC (100000 = 6250*16)
    int beg = g_rowstart[n], end = g_rowstart[n + 1];
    const float4* hb = (const float4*)h;
    float4 a0 = make_float4(0.f, 0.f, 0.f, 0.f);
    float4 a1 = make_float4(0.f, 0.f, 0.f, 0.f);
    int i = beg;
    for (; i + 4 <= end; i += 4) {
        int s0 = __ldg(&g_srcs[i]);
        int s1 = __ldg(&g_srcs[i + 1]);
        int s2 = __ldg(&g_srcs[i + 2]);
        int s3 = __ldg(&g_srcs[i + 3]);
        float4 v0 = hb[(size_t)s0 * 32 + lane];
        float4 v1 = hb[(size_t)s1 * 32 + lane];
        float4 v2 = hb[(size_t)s2 * 32 + lane];
        float4 v3 = hb[(size_t)s3 * 32 + lane];
        a0.x += v0.x; a0.y += v0.y; a0.z += v0.z; a0.w += v0.w;
        a1.x += v1.x; a1.y += v1.y; a1.z += v1.z; a1.w += v1.w;
        a0.x += v2.x; a0.y += v2.y; a0.z += v2.z; a0.w += v2.w;
        a1.x += v3.x; a1.y += v3.y; a1.z += v3.z; a1.w += v3.w;
    }
    for (; i < end; i++) {
        int s0 = __ldg(&g_srcs[i]);
        float4 v0 = hb[(size_t)s0 * 32 + lane];
        a0.x += v0.x; a0.y += v0.y; a0.z += v0.z; a0.w += v0.w;
    }
    a0.x += a1.x; a0.y += a1.y; a0.z += a1.z; a0.w += a1.w;

    {
        int g = w & 7, rh = (w >> 3) & 1;
        int kt = lane >> 2, p0 = (lane & 3) * 2;
        uint32_t h0, l0, h1, l1;
        pack_pair(a0.x, a0.y, h0, l0);
        pack_pair(a0.z, a0.w, h1, l1);
        int w0 = (g * 4 + (p0 & 3)) * 4 + ((p0 >> 2) << 1) + rh;
        int p1 = p0 + 1;
        int w1 = (g * 4 + (p1 & 3)) * 4 + ((p1 >> 2) << 1) + rh;
        stg[kt * 128 + w0] = h0;
        stg[kt * 128 + w1] = h1;
        stg[1024 + kt * 128 + w0] = l0;
        stg[1024 + kt * 128 + w1] = l1;
    }
    __syncthreads();

    int tile = blockIdx.x >> 3;
    int rb = blockIdx.x & 7;
    int t = threadIdx.x;
    int q = t & 255, kt2 = q >> 5, w4 = q & 31;
    const uint4* src = (const uint4*)(stg + ((t < 256) ? 0 : 1024));
    uint32_t* dst = (t < 256) ? g_AHi : g_ALo;
    *(uint4*)(dst + ((size_t)tile * 8 + kt2) * 1024 + rb * 128 + w4 * 4) = src[q];
}

// ---------------- weight precompute ----------------
__global__ void k_prep_wc(const float* __restrict__ Wmp, const float* __restrict__ Wih) {
    int idx = blockIdx.x * blockDim.x + threadIdx.x;
    if (idx >= STEPSC * H3C * HC) return;
    int k = idx % HC;
    int j = (idx / HC) % H3C;
    int s = idx / (HC * H3C);
    const float4* wm = (const float4*)(Wmp + ((size_t)s * HC + k) * HC);
    const float4* wi = (const float4*)(Wih + (size_t)j * HC);
    float acc = 0.f;
#pragma unroll
    for (int m = 0; m < HC / 4; m++) {
        float4 a = wm[m], b = wi[m];
        acc += a.x * b.x + a.y * b.y + a.z * b.z + a.w * b.w;
    }
    g_WcG[idx] = acc;
}

// B fragment images (phase-split): [s][ys][kt][nb' 0..11][lane][j].
__global__ void k_prep_bimg(const float* __restrict__ Whh) {
    int idx = blockIdx.x * blockDim.x + threadIdx.x;
    if (idx >= STEPSC * BIMG_STEP_W) return;
    int j = idx & 1;
    int lane = (idx >> 1) & 31;
    int t = idx >> 6;
    int nbp = t % 12; t /= 12;
    int kt = t % 16;  t /= 16;
    int ys = t % 4;
    int s = t / 4;
    int g = lane >> 2, tI = lane & 3;
    int k0 = kt * 16 + 2 * tI + 8 * j;
    float v[2];
#pragma unroll
    for (int e = 0; e < 2; e++) {
        int k = k0 + e;
        float val;
        if (nbp < 8) {
            int c = nbp * 8 + g;
            int f = ys * 32 + (c >> 1);
            int gate = c & 1;
            val = (k < HC) ? g_WcG[((size_t)s * H3C + gate * HC + f) * HC + k]
                           : Whh[(size_t)(gate * HC + f) * HC + (k - HC)];
        } else {
            int f = ys * 32 + (nbp - 8) * 8 + g;
            val = (k < HC) ? g_WcG[((size_t)s * H3C + 2 * HC + f) * HC + k]
                           : Whh[(size_t)(2 * HC + f) * HC + (k - HC)];
        }
        v[e] = val;
    }
    uint32_t hi, lo;
    pack_pair(v[0], v[1], hi, lo);
    g_BHi[idx] = hi;
    g_BLo[idx] = lo;
}

// ---------------- input layer: h = tanh(x @ W_in), fused fragment-image writes ----------------
__global__ void __launch_bounds__(256) k_input(
    const float* __restrict__ x, const float* __restrict__ Win, float* __restrict__ h,
    uint32_t* __restrict__ Hi, uint32_t* __restrict__ Lo)
{
    __shared__ float sw[F_INC * HC];  // [k][c], 32KB
    int tid = threadIdx.x;
    for (int i = tid; i < F_INC * HC; i += 256) sw[i] = Win[i];
    __syncthreads();
    int n = blockIdx.x * 256 + tid;
    if (n >= N_NODESC) return;

    float4 xr[16];
    const float4* xp = (const float4*)(x + (size_t)n * F_INC);
#pragma unroll
    for (int j = 0; j < 16; j++) xr[j] = xp[j];

    int tile = n >> 7, rr = n & 127;
    float* hrow = h + (size_t)n * HC;

#pragma unroll 1
    for (int cg = 0; cg < 8; cg++) {
        float acc[16];
#pragma unroll
        for (int j = 0; j < 16; j++) acc[j] = 0.f;
#pragma unroll
        for (int k4 = 0; k4 < 16; k4++) {
            float4 xv4 = xr[k4];
            float xs[4] = {xv4.x, xv4.y, xv4.z, xv4.w};
#pragma unroll
            for (int kk = 0; kk < 4; kk++) {
                int k = k4 * 4 + kk;
                const float4* wp = (const float4*)(sw + k * HC + cg * 16);
#pragma unroll
                for (int j4 = 0; j4 < 4; j4++) {
                    float4 w = wp[j4];
                    acc[j4 * 4 + 0] += xs[kk] * w.x;
                    acc[j4 * 4 + 1] += xs[kk] * w.y;
                    acc[j4 * 4 + 2] += xs[kk] * w.z;
                    acc[j4 * 4 + 3] += xs[kk] * w.w;
                }
            }
        }
        size_t base = ((size_t)tile * 8 + cg) * 1024;
#pragma unroll
        for (int j = 0; j < 4; j++) {
            float4 o;
            o.x = tanhf(acc[j * 4 + 0]);
            o.y = tanhf(acc[j * 4 + 1]);
            o.z = tanhf(acc[j * 4 + 2]);
            o.w = tanhf(acc[j * 4 + 3]);
            *(float4*)(hrow + cg * 16 + j * 4) = o;
            store_split4(Hi, Lo, base, rr, j * 2, o);
        }
    }
}

// ---------------- bf16x3 mma.sync fused GEMM + GRU, phase-split columns ----------------
// hprev staged via cp.async inside CHUNK 1's group: the c=0 wait drains only g0,
// so the first MMA is ungated and the 18KB hp transfer hides behind chunk-0 compute.
__global__ void __launch_bounds__(256, 2) k_gemm(
    const float* __restrict__ hin, float* __restrict__ hout,
    const uint32_t* __restrict__ Bhi, const uint32_t* __restrict__ Blo,
    const uint32_t* __restrict__ HhiIn, const uint32_t* __restrict__ HloIn,
    uint32_t* __restrict__ HhiOut, uint32_t* __restrict__ HloOut,
    const float* __restrict__ bih, const float* __restrict__ bhh,
    const void* __restrict__ batch, int write_img)
{
    extern __shared__ uint32_t smu[];  // 3 stages x STAGE_W | hp [128][36] floats
    __shared__ float sbias[4][32];

    const int tid = threadIdx.x;
    const int lane = tid & 31;
    const int warp = tid >> 5;
    const int warpM = warp & 1;
    const int warpN = warp >> 1;
    const int tile = blockIdx.x;
    const int row0 = tile * 128;
    const int ys = blockIdx.y;
    float* sHp = (float*)(smu + 3 * STAGE_W);

    if (tid < 32) {
        int f = ys * 32 + tid;
        sbias[0][tid] = bih[f] + bhh[f];
        sbias[1][tid] = bih[HC + f] + bhh[HC + f];
        sbias[2][tid] = bih[2 * HC + f];
        sbias[3][tid] = bhh[2 * HC + f];
    }

    const uint32_t* Bh = Bhi + (size_t)ys * 16 * BIMG_KT_W;
    const uint32_t* Bl = Blo + (size_t)ys * 16 * BIMG_KT_W;
    const uint32_t smem_base = smem_u32(smu);
    const uint32_t hp_base = smem_base + (3 * STAGE_W) * 4;

    auto issue = [&](int c) {
        uint32_t d = smem_base + ((c % 3) * STAGE_W) * 4;
#pragma unroll
        for (int kk = 0; kk < 2; kk++) {
            int kt = 2 * c + kk;
            const uint32_t *ah, *al;
            if (kt < 8) {
                ah = g_AHi + ((size_t)tile * 8 + kt) * 1024;
                al = g_ALo + ((size_t)tile * 8 + kt) * 1024;
            } else {
                ah = HhiIn + ((size_t)tile * 8 + (kt - 8)) * 1024;
                al = HloIn + ((size_t)tile * 8 + (kt - 8)) * 1024;
            }
            cpasync16(d + kk * 4096 + tid * 16,        ah + tid * 4);
            cpasync16(d + 8192 + kk * 4096 + tid * 16, al + tid * 4);
            if (tid < 192) {
                cpasync16(d + 16384 + kk * 3072 + tid * 16, Bh + (size_t)kt * BIMG_KT_W + tid * 4);
                cpasync16(d + 22528 + kk * 3072 + tid * 16, Bl + (size_t)kt * BIMG_KT_W + tid * 4);
            }
        }
        if (c == 1) {
            // hprev block: 128 rows x 32 floats, padded stride 36 (16B-aligned rows).
            // Drained by the c=1 wait, well before the epilogue; overlaps chunk-0 compute.
#pragma unroll
            for (int rep = 0; rep < 4; rep++) {
                int idx = tid + rep * 256;       // 0..1023
                int row = idx >> 3, ch = idx & 7;
                int grow = row0 + row;
                if (grow >= N_NODESC) grow = N_NODESC - 1;  // clamp: finite, row-local
                cpasync16(hp_base + (row * 36 + ch * 4) * 4,
                          hin + (size_t)grow * HC + ys * 32 + ch * 4);
            }
        }
        cp_commit();
    };

    float acc_rz0[4][4], acc_rz1[4][4], acc_in[4][4], acc_hn[4][4];
#pragma unroll
    for (int mt = 0; mt < 4; mt++)
#pragma unroll
        for (int r = 0; r < 4; r++) {
            acc_rz0[mt][r] = 0.f; acc_rz1[mt][r] = 0.f;
            acc_in[mt][r] = 0.f;  acc_hn[mt][r] = 0.f;
        }

    issue(0);
    issue(1);

    for (int c = 0; c < 8; c++) {
        if (c < 7) cp_wait1();
        else cp_wait0();
        __syncthreads();
        if (c <= 5) issue(c + 2);

        const uint32_t* st = smu + (c % 3) * STAGE_W;
        bool ph0 = (c < 4);
#pragma unroll
        for (int kk = 0; kk < 2; kk++) {
            const uint32_t* Ahw = st + kk * 1024;
            const uint32_t* Alw = st + 2048 + kk * 1024;
            const uint32_t* Bhw = st + 4096 + kk * BIMG_KT_W;
            const uint32_t* Blw = st + 5632 + kk * BIMG_KT_W;

            uint2 rz0h = *(const uint2*)(Bhw + (2 * warpN) * 64 + lane * 2);
            uint2 rz0l = *(const uint2*)(Blw + (2 * warpN) * 64 + lane * 2);
            uint2 rz1h = *(const uint2*)(Bhw + (2 * warpN + 1) * 64 + lane * 2);
            uint2 rz1l = *(const uint2*)(Blw + (2 * warpN + 1) * 64 + lane * 2);
            uint2 xh   = *(const uint2*)(Bhw + (8 + warpN) * 64 + lane * 2);
            uint2 xl   = *(const uint2*)(Blw + (8 + warpN) * 64 + lane * 2);
#pragma unroll
            for (int mt = 0; mt < 4; mt++) {
                int rb = warpM * 4 + mt;
                uint4 ah = *(const uint4*)(Ahw + rb * 128 + lane * 4);
                uint4 al = *(const uint4*)(Alw + rb * 128 + lane * 4);
                mma3(acc_rz0[mt], ah, al, rz0h, rz0l);
                mma3(acc_rz1[mt], ah, al, rz1h, rz1l);
                if (ph0) mma3(acc_in[mt], ah, al, xh, xl);
                else     mma3(acc_hn[mt], ah, al, xh, xl);
            }
        }
    }
    __syncthreads();   // all compute done before sOut aliases pipeline smem

    // ---------------- fused GRU epilogue (phase-split layout) ----------------
    float* sOut = (float*)smu;  // [128][36], aliases stage smem (hp block untouched)
    const int g = lane >> 2;
    const int tI = lane & 3;
    const bool use1 = (tI >= 2);

#pragma unroll
    for (int mt = 0; mt < 4; mt++) {
        int rowl = warpM * 64 + mt * 16 + g;
#pragma unroll
        for (int e = 0; e < 2; e++) {
            int u = 2 * tI + e;
            int src = g * 4 + (u & 3);
            float v0[4], v1[4];
#pragma unroll
            for (int i = 0; i < 4; i++) {
                v0[i] = __shfl_sync(0xffffffffu, acc_rz0[mt][i], src);
                v1[i] = __shfl_sync(0xffffffffu, acc_rz1[mt][i], src);
            }
            float Sr_a = use1 ? v1[0] : v0[0];
            float Sz_a = use1 ? v1[1] : v0[1];
            float Sr_b = use1 ? v1[2] : v0[2];
            float Sz_b = use1 ? v1[3] : v0[3];
            float in_a = acc_in[mt][e],     in_b = acc_in[mt][2 + e];
            float hn_a = acc_hn[mt][e],     hn_b = acc_hn[mt][2 + e];
            int fl = warpN * 8 + u;
            float hpa = sHp[rowl * 36 + fl];
            float hpb = sHp[(rowl + 8) * 36 + fl];
            float ra = sigf(Sr_a + sbias[0][fl]);
            float za = sigf(Sz_a + sbias[1][fl]);
            float na = tanhfast(in_a + sbias[2][fl] + ra * (hn_a + sbias[3][fl]));
            float rb2 = sigf(Sr_b + sbias[0][fl]);
            float zb = sigf(Sz_b + sbias[1][fl]);
            float nb2 = tanhfast(in_b + sbias[2][fl] + rb2 * (hn_b + sbias[3][fl]));
            sOut[rowl * 36 + fl]       = (1.f - za) * na + za * hpa;
            sOut[(rowl + 8) * 36 + fl] = (1.f - zb) * nb2 + zb * hpb;
        }
    }
    __syncthreads();

    // hout (fp32) writeback / pool accumulation
#pragma unroll
    for (int rep = 0; rep < 4; rep++) {
        int idx = tid + rep * 256;
        int row = idx >> 3, q = idx & 7;
        int grow = row0 + row;
        if (grow < N_NODESC) {
            float4 o = *(const float4*)(sOut + row * 36 + q * 4);
            if (write_img) {
                *(float4*)(hout + (size_t)grow * HC + ys * 32 + q * 4) = o;
            } else {
                int gidx = load_idx(batch, grow, g_is64);
                red4(&g_sums[gidx * HC + ys * 32 + q * 4], o);
            }
        }
    }

    // coalesced h-image writeback from sOut (2 kt blocks owned by this CTA)
    if (write_img) {
        int gq = (tid & 31) >> 2;
        int pm = tid & 3;
        int rb2 = tid >> 5;
        int rowA = rb2 * 16 + gq;
        int rowB = rowA + 8;
#pragma unroll
        for (int kb = 0; kb < 2; kb++) {
            int fb = kb * 16;
            float a0v = sOut[rowA * 36 + fb + 2 * pm],     a1v = sOut[rowA * 36 + fb + 2 * pm + 1];
            float b0v = sOut[rowB * 36 + fb + 2 * pm],     b1v = sOut[rowB * 36 + fb + 2 * pm + 1];
            float c0v = sOut[rowA * 36 + fb + 2 * pm + 8], c1v = sOut[rowA * 36 + fb + 2 * pm + 9];
            float d0v = sOut[rowB * 36 + fb + 2 * pm + 8], d1v = sOut[rowB * 36 + fb + 2 * pm + 9];
            uint4 hi4, lo4;
            pack_pair(a0v, a1v, hi4.x, lo4.x);
            pack_pair(b0v, b1v, hi4.y, lo4.y);
            pack_pair(c0v, c1v, hi4.z, lo4.z);
            pack_pair(d0v, d1v, hi4.w, lo4.w);
            size_t base = ((size_t)tile * 8 + ys * 2 + kb) * 1024;
            *(uint4*)(HhiOut + base + tid * 4) = hi4;
            *(uint4*)(HloOut + base + tid * 4) = lo4;
        }
    }
}

// ---------------- output ----------------
__global__ void k_out(const float* __restrict__ Wp, const float* __restrict__ bp,
                      float* __restrict__ out) {
    int g = blockIdx.x;
    int t = threadIdx.x;  // 128
    float c = fmaxf(g_cnt[g], 1.0f);
    float pooled = g_sums[g * HC + t] / c;
    float v = fmaxf(pooled, 0.f) * Wp[t];
    __shared__ float red[4];
#pragma unroll
    for (int o = 16; o > 0; o >>= 1) v += __shfl_down_sync(0xffffffff, v, o);
    if ((t & 31) == 0) red[t >> 5] = v;
    __syncthreads();
    if (t == 0) out[g] = red[0] + red[1] + red[2] + red[3] + bp[0];
}

// ---------------- launch ----------------
extern "C" void kernel_launch(void* const* d_in, const int* in_sizes, int n_in,
                              void* d_out, int out_size) {
    const float* x    = (const float*)d_in[0];
    const void*  ei   = d_in[1];
    const void*  batch= d_in[2];
    const float* W_in = (const float*)d_in[3];
    const float* W_mp = (const float*)d_in[4];
    const float* W_ih = (const float*)d_in[5];
    const float* W_hh = (const float*)d_in[6];
    const float* b_ih = (const float*)d_in[7];
    const float* b_hh = (const float*)d_in[8];
    const float* W_p  = (const float*)d_in[9];
    const float* b_p  = (const float*)d_in[10];
    float* out = (float*)d_out;

    void *hA, *hB, *sumsPtr, *cntPtr, *degPtr, *curPtr;
    void *bHiP, *bLoP, *hHiP, *hLoP;
    cudaGetSymbolAddress(&hA, g_hA);
    cudaGetSymbolAddress(&hB, g_hB);
    cudaGetSymbolAddress(&sumsPtr, g_sums);
    cudaGetSymbolAddress(&cntPtr, g_cnt);
    cudaGetSymbolAddress(&degPtr, g_deg);
    cudaGetSymbolAddress(&curPtr, g_cursor);
    cudaGetSymbolAddress(&bHiP, g_BHi);
    cudaGetSymbolAddress(&bLoP, g_BLo);
    cudaGetSymbolAddress(&hHiP, g_HHi);
    cudaGetSymbolAddress(&hLoP, g_HLo);
    const uint32_t* BHi = (const uint32_t*)bHiP;
    const uint32_t* BLo = (const uint32_t*)bLoP;
    uint32_t* HHi = (uint32_t*)hHiP;  // [2][AIMG_WORDS]
    uint32_t* HLo = (uint32_t*)hLoP;

    cudaFuncSetAttribute(k_gemm, cudaFuncAttributeMaxDynamicSharedMemorySize, SMEM_DYN);

    k_detect<<<1, 256>>>((const int*)ei);

    // pooled-sum scratch + per-graph counts
    cudaMemsetAsync(sumsPtr, 0, (size_t)N_GRAPHSC * HC * sizeof(float), 0);
    cudaMemsetAsync(cntPtr, 0, (size_t)N_GRAPHSC * sizeof(float), 0);
    k_cnt<<<(N_NODESC + 255) / 256, 256>>>(batch);

    // CSR build
    cudaMemsetAsync(degPtr, 0, N_NODESC * sizeof(int), 0);
    cudaMemsetAsync(curPtr, 0, N_NODESC * sizeof(int), 0);
    k_deg<<<(N_EDGESC + 255) / 256, 256>>>(ei);
    k_scan1<<<NSCANB, 256>>>();
    k_scan2<<<1, 32>>>();
    k_scan3<<<NSCANB, 256>>>();
    k_fill<<<(N_EDGESC + 255) / 256, 256>>>(ei);

    // weights
    k_prep_wc<<<(STEPSC * H3C * HC + 255) / 256, 256>>>(W_mp, W_ih);
    k_prep_bimg<<<(STEPSC * BIMG_STEP_W + 255) / 256, 256>>>(W_hh);

    // input layer (writes h AND the step-0 h fragment images)
    k_input<<<(N_NODESC + 255) / 256, 256>>>(x, W_in, (float*)hA, HHi, HLo);

    float* hcur = (float*)hA;
    float* hnext = (float*)hB;
    for (int s = 0; s < STEPSC; s++) {
        int pin = s & 1, pout = (s + 1) & 1;
        k_gather<<<N_NODESC / 16, 512>>>(hcur);
        dim3 grid(NTILES, 4);
        k_gemm<<<grid, 256, SMEM_DYN>>>(
            hcur, hnext,
            BHi + (size_t)s * BIMG_STEP_W, BLo + (size_t)s * BIMG_STEP_W,
            HHi + (size_t)pin * AIMG_WORDS, HLo + (size_t)pin * AIMG_WORDS,
            HHi + (size_t)pout * AIMG_WORDS, HLo + (size_t)pout * AIMG_WORDS,
            b_ih, b_hh, batch, (s < STEPSC - 1) ? 1 : 0);
        float* tmp = hcur; hcur = hnext; hnext = tmp;
    }
    k_out<<<N_GRAPHSC, 128>>>(W_p, b_p, out);
}

// round 16
// speedup vs baseline: 1.1200x; 1.0065x over previous
#include <cuda_runtime.h>
#include <cstdint>

#define N_NODESC 100000
#define N_EDGESC 1600000
#define N_GRAPHSC 512
#define F_INC 64
#define HC 128
#define H3C 384
#define STEPSC 6
#define NTILES 782                         // ceil(100000/128)
#define AIMG_WORDS ((size_t)NTILES * 8 * 1024)
#define BIMG_KT_W 768                      // 12 n-blocks x 64 words
#define BIMG_STEP_W (4 * 16 * BIMG_KT_W)   // 49152 words per step per image
#define STAGE_W 7168                       // Ahi 2048 | Alo 2048 | Bhi 1536 | Blo 1536
#define HP_W (128 * 36)                    // hprev smem block (stride 36: conflict-free, 16B rows)
#define SMEM_DYN ((3 * STAGE_W + HP_W) * 4)  // 104448 B
#define NSCANB 98                          // ceil(100000/1024)

// ---------------- device scratch ----------------
__device__ float g_hA[(size_t)N_NODESC * HC];
__device__ float g_hB[(size_t)N_NODESC * HC];
__device__ float g_WcG[(size_t)STEPSC * H3C * HC];
__device__ __align__(16) uint32_t g_AHi[AIMG_WORDS];     // agg fragment image (bf16x2 hi)
__device__ __align__(16) uint32_t g_ALo[AIMG_WORDS];
__device__ __align__(16) uint32_t g_HHi[2][AIMG_WORDS];  // h fragment images, step parity
__device__ __align__(16) uint32_t g_HLo[2][AIMG_WORDS];
__device__ __align__(16) uint32_t g_BHi[(size_t)STEPSC * BIMG_STEP_W];
__device__ __align__(16) uint32_t g_BLo[(size_t)STEPSC * BIMG_STEP_W];
__device__ float g_sums[N_GRAPHSC * HC];
__device__ float g_cnt[N_GRAPHSC];
__device__ int   g_is64;
// CSR
__device__ int g_deg[N_NODESC];
__device__ int g_cursor[N_NODESC];
__device__ int g_rowstart[N_NODESC + 1];
__device__ __align__(16) int g_srcs[N_EDGESC];
__device__ int g_bsum[NSCANB];

// ---------------- helpers ----------------
__device__ __forceinline__ uint32_t smem_u32(const void* p) {
    uint32_t a;
    asm("{ .reg .u64 t; cvta.to.shared.u64 t, %1; cvt.u32.u64 %0, t; }" : "=r"(a) : "l"(p));
    return a;
}
__device__ __forceinline__ uint32_t pack_bf2(float lo, float hi) {
    uint32_t r;
    asm("cvt.rn.bf16x2.f32 %0, %1, %2;" : "=r"(r) : "f"(hi), "f"(lo));
    return r;
}
__device__ __forceinline__ float bf2_low(uint32_t v)  { return __uint_as_float(v << 16); }
__device__ __forceinline__ float bf2_high(uint32_t v) { return __uint_as_float(v & 0xffff0000u); }
__device__ __forceinline__ void pack_pair(float v0, float v1, uint32_t& hi, uint32_t& lo) {
    hi = pack_bf2(v0, v1);
    lo = pack_bf2(v0 - bf2_low(hi), v1 - bf2_high(hi));
}
__device__ __forceinline__ void red4(float* p, float4 v) {
    asm volatile("red.global.add.v4.f32 [%0], {%1,%2,%3,%4};"
                 :: "l"(p), "f"(v.x), "f"(v.y), "f"(v.z), "f"(v.w) : "memory");
}
__device__ __forceinline__ int load_idx(const void* p, long long i, int is64) {
    if (is64) return (int)((const long long*)p)[i];
    return ((const int*)p)[i];
}
__device__ __forceinline__ float sigf(float x) {
    return __fdividef(1.0f, 1.0f + __expf(-x));
}
__device__ __forceinline__ float tanhfast(float x) {
    float e = __expf(2.0f * x);
    return 1.0f - __fdividef(2.0f, e + 1.0f);
}
__device__ __forceinline__ void mma_bf16(float* d, uint32_t a0, uint32_t a1, uint32_t a2,
                                         uint32_t a3, uint32_t b0, uint32_t b1) {
    asm volatile(
        "mma.sync.aligned.m16n8k16.row.col.f32.bf16.bf16.f32 "
        "{%0,%1,%2,%3}, {%4,%5,%6,%7}, {%8,%9}, {%0,%1,%2,%3};"
        : "+f"(d[0]), "+f"(d[1]), "+f"(d[2]), "+f"(d[3])
        : "r"(a0), "r"(a1), "r"(a2), "r"(a3), "r"(b0), "r"(b1));
}
__device__ __forceinline__ void mma3(float* d, const uint4& ah, const uint4& al,
                                     const uint2& bh, const uint2& bl) {
    mma_bf16(d, ah.x, ah.y, ah.z, ah.w, bh.x, bh.y);
    mma_bf16(d, ah.x, ah.y, ah.z, ah.w, bl.x, bl.y);
    mma_bf16(d, al.x, al.y, al.z, al.w, bh.x, bh.y);
}
__device__ __forceinline__ void cpasync16(uint32_t saddr, const void* g) {
    asm volatile("cp.async.cg.shared.global [%0], [%1], 16;" :: "r"(saddr), "l"(g) : "memory");
}
__device__ __forceinline__ void cp_commit() { asm volatile("cp.async.commit_group;" ::: "memory"); }
__device__ __forceinline__ void cp_wait1()  { asm volatile("cp.async.wait_group 1;" ::: "memory"); }
__device__ __forceinline__ void cp_wait0()  { asm volatile("cp.async.wait_group 0;" ::: "memory"); }

// Fragment-image word offset for (row-in-tile rr, pair p) within a 1024-word kt block.
__device__ __forceinline__ int aimg_word(int rr, int p) {
    int g = rr & 7, rh = (rr >> 3) & 1, rb = rr >> 4;
    return rb * 128 + (g * 4 + (p & 3)) * 4 + (p >> 2) * 2 + rh;
}

__device__ __forceinline__ void store_split4(uint32_t* Hi, uint32_t* Lo, size_t base,
                                             int rr, int p0, float4 v) {
    uint32_t h0, l0, h1, l1;
    pack_pair(v.x, v.y, h0, l0);
    pack_pair(v.z, v.w, h1, l1);
    int w0 = aimg_word(rr, p0), w1 = aimg_word(rr, p0 + 1);
    Hi[base + w0] = h0; Hi[base + w1] = h1;
    Lo[base + w0] = l0; Lo[base + w1] = l1;
}

// ---------------- index dtype sniffer ----------------
__global__ void k_detect(const int* __restrict__ ei) {
    int any = 0;
    for (int i = threadIdx.x; i < 2048; i += blockDim.x) any |= ei[2 * i + 1];
    any = __syncthreads_or(any);
    if (threadIdx.x == 0) g_is64 = (any == 0) ? 1 : 0;
}

// ---------------- CSR build ----------------
// Vectorized: 4 edges per thread.
__global__ void k_deg(const void* __restrict__ ei) {
    int e4 = blockIdx.x * blockDim.x + threadIdx.x;
    if (e4 >= N_EDGESC / 4) return;
    if (g_is64) {
        const longlong2* p = (const longlong2*)ei + N_EDGESC / 2 + e4 * 2;
        longlong2 a = p[0], b = p[1];
        atomicAdd(&g_deg[(int)a.x], 1);
        atomicAdd(&g_deg[(int)a.y], 1);
        atomicAdd(&g_deg[(int)b.x], 1);
        atomicAdd(&g_deg[(int)b.y], 1);
    } else {
        int4 d = ((const int4*)ei)[N_EDGESC / 4 + e4];
        atomicAdd(&g_deg[d.x], 1);
        atomicAdd(&g_deg[d.y], 1);
        atomicAdd(&g_deg[d.z], 1);
        atomicAdd(&g_deg[d.w], 1);
    }
}

__global__ void k_scan1() {
    __shared__ int sred[8];
    int b = blockIdx.x, t = threadIdx.x;
    int i0 = b * 1024 + t * 4;
    int s = 0;
#pragma unroll
    for (int j = 0; j < 4; j++) {
        int i = i0 + j;
        if (i < N_NODESC) s += g_deg[i];
    }
#pragma unroll
    for (int o = 16; o > 0; o >>= 1) s += __shfl_down_sync(0xffffffffu, s, o);
    if ((t & 31) == 0) sred[t >> 5] = s;
    __syncthreads();
    if (t == 0) {
        int tot = 0;
#pragma unroll
        for (int j = 0; j < 8; j++) tot += sred[j];
        g_bsum[b] = tot;
    }
}

__global__ void k_scan2() {
    int lane = threadIdx.x;  // 32
    int base = 0;
    for (int c = 0; c < 4; c++) {
        int i = c * 32 + lane;
        int v = (i < NSCANB) ? g_bsum[i] : 0;
        int s = v;
#pragma unroll
        for (int o = 1; o < 32; o <<= 1) {
            int t = __shfl_up_sync(0xffffffffu, s, o);
            if (lane >= o) s += t;
        }
        if (i < NSCANB) g_bsum[i] = base + (s - v);  // exclusive
        base += __shfl_sync(0xffffffffu, s, 31);
    }
    if (lane == 0) g_rowstart[0] = 0;
}

__global__ void k_scan3() {
    __shared__ int swarp[8];
    int b = blockIdx.x, t = threadIdx.x;
    int i0 = b * 1024 + t * 4;
    int d[4], ts = 0;
#pragma unroll
    for (int j = 0; j < 4; j++) {
        d[j] = (i0 + j < N_NODESC) ? g_deg[i0 + j] : 0;
        ts += d[j];
    }
    int s = ts;
#pragma unroll
    for (int o = 1; o < 32; o <<= 1) {
        int v = __shfl_up_sync(0xffffffffu, s, o);
        if ((t & 31) >= o) s += v;
    }
    if ((t & 31) == 31) swarp[t >> 5] = s;
    __syncthreads();
    int wpre = 0;
    for (int j = 0; j < (t >> 5); j++) wpre += swarp[j];
    int run = g_bsum[b] + wpre + (s - ts);
#pragma unroll
    for (int j = 0; j < 4; j++) {
        run += d[j];
        if (i0 + j < N_NODESC) g_rowstart[i0 + j + 1] = run;
    }
}

__global__ void k_fill(const void* __restrict__ ei) {
    int e = blockIdx.x * blockDim.x + threadIdx.x;
    if (e >= N_EDGESC) return;
    int is64 = g_is64;
    int s = load_idx(ei, e, is64);
    int d = load_idx(ei, (long long)N_EDGESC + e, is64);
    int pos = g_rowstart[d] + atomicAdd(&g_cursor[d], 1);
    g_srcs[pos] = s;
}

// ---------------- graph node counts (launch-invariant) ----------------
__global__ void k_cnt(const void* __restrict__ batch) {
    int i = blockIdx.x * blockDim.x + threadIdx.x;
    if (i >= N_NODESC) return;
    atomicAdd(&g_cnt[load_idx(batch, i, g_is64)], 1.0f);
}

// ---------------- gather: agg[n] = sum h[src]; smem-staged coalesced image writes ----------------
// R12-validated structure; idx loads vectorized (aligned int4, 4 indices per LDG.128).
__global__ void __launch_bounds__(512) k_gather(const float* __restrict__ h) {
    __shared__ uint32_t stg[2048];  // hi [0,1024) | lo [1024,2048)
    int w = threadIdx.x >> 5, lane = threadIdx.x & 31;
    int n = blockIdx.x * 16 + w;    // always < N_NODESC (100000 = 6250*16)
    int beg = g_rowstart[n], end = g_rowstart[n + 1];
    const float4* hb = (const float4*)h;
    float4 a0 = make_float4(0.f, 0.f, 0.f, 0.f);
    float4 a1 = make_float4(0.f, 0.f, 0.f, 0.f);
    int i = beg;
    // peel to 16B alignment of g_srcs + i
    for (; i < end && (i & 3); i++) {
        int s0 = __ldg(&g_srcs[i]);
        float4 v0 = hb[(size_t)s0 * 32 + lane];
        a0.x += v0.x; a0.y += v0.y; a0.z += v0.z; a0.w += v0.w;
    }
    for (; i + 4 <= end; i += 4) {
        int4 s4 = *(const int4*)(g_srcs + i);
        float4 v0 = hb[(size_t)s4.x * 32 + lane];
        float4 v1 = hb[(size_t)s4.y * 32 + lane];
        float4 v2 = hb[(size_t)s4.z * 32 + lane];
        float4 v3 = hb[(size_t)s4.w * 32 + lane];
        a0.x += v0.x; a0.y += v0.y; a0.z += v0.z; a0.w += v0.w;
        a1.x += v1.x; a1.y += v1.y; a1.z += v1.z; a1.w += v1.w;
        a0.x += v2.x; a0.y += v2.y; a0.z += v2.z; a0.w += v2.w;
        a1.x += v3.x; a1.y += v3.y; a1.z += v3.z; a1.w += v3.w;
    }
    for (; i < end; i++) {
        int s0 = __ldg(&g_srcs[i]);
        float4 v0 = hb[(size_t)s0 * 32 + lane];
        a0.x += v0.x; a0.y += v0.y; a0.z += v0.z; a0.w += v0.w;
    }
    a0.x += a1.x; a0.y += a1.y; a0.z += a1.z; a0.w += a1.w;

    {
        int g = w & 7, rh = (w >> 3) & 1;
        int kt = lane >> 2, p0 = (lane & 3) * 2;
        uint32_t h0, l0, h1, l1;
        pack_pair(a0.x, a0.y, h0, l0);
        pack_pair(a0.z, a0.w, h1, l1);
        int w0 = (g * 4 + (p0 & 3)) * 4 + ((p0 >> 2) << 1) + rh;
        int p1 = p0 + 1;
        int w1 = (g * 4 + (p1 & 3)) * 4 + ((p1 >> 2) << 1) + rh;
        stg[kt * 128 + w0] = h0;
        stg[kt * 128 + w1] = h1;
        stg[1024 + kt * 128 + w0] = l0;
        stg[1024 + kt * 128 + w1] = l1;
    }
    __syncthreads();

    int tile = blockIdx.x >> 3;
    int rb = blockIdx.x & 7;
    int t = threadIdx.x;
    int q = t & 255, kt2 = q >> 5, w4 = q & 31;
    const uint4* src = (const uint4*)(stg + ((t < 256) ? 0 : 1024));
    uint32_t* dst = (t < 256) ? g_AHi : g_ALo;
    *(uint4*)(dst + ((size_t)tile * 8 + kt2) * 1024 + rb * 128 + w4 * 4) = src[q];
}

// ---------------- weight precompute ----------------
__global__ void k_prep_wc(const float* __restrict__ Wmp, const float* __restrict__ Wih) {
    int idx = blockIdx.x * blockDim.x + threadIdx.x;
    if (idx >= STEPSC * H3C * HC) return;
    int k = idx % HC;
    int j = (idx / HC) % H3C;
    int s = idx / (HC * H3C);
    const float4* wm = (const float4*)(Wmp + ((size_t)s * HC + k) * HC);
    const float4* wi = (const float4*)(Wih + (size_t)j * HC);
    float acc = 0.f;
#pragma unroll
    for (int m = 0; m < HC / 4; m++) {
        float4 a = wm[m], b = wi[m];
        acc += a.x * b.x + a.y * b.y + a.z * b.z + a.w * b.w;
    }
    g_WcG[idx] = acc;
}

// B fragment images (phase-split): [s][ys][kt][nb' 0..11][lane][j].
__global__ void k_prep_bimg(const float* __restrict__ Whh) {
    int idx = blockIdx.x * blockDim.x + threadIdx.x;
    if (idx >= STEPSC * BIMG_STEP_W) return;
    int j = idx & 1;
    int lane = (idx >> 1) & 31;
    int t = idx >> 6;
    int nbp = t % 12; t /= 12;
    int kt = t % 16;  t /= 16;
    int ys = t % 4;
    int s = t / 4;
    int g = lane >> 2, tI = lane & 3;
    int k0 = kt * 16 + 2 * tI + 8 * j;
    float v[2];
#pragma unroll
    for (int e = 0; e < 2; e++) {
        int k = k0 + e;
        float val;
        if (nbp < 8) {
            int c = nbp * 8 + g;
            int f = ys * 32 + (c >> 1);
            int gate = c & 1;
            val = (k < HC) ? g_WcG[((size_t)s * H3C + gate * HC + f) * HC + k]
                           : Whh[(size_t)(gate * HC + f) * HC + (k - HC)];
        } else {
            int f = ys * 32 + (nbp - 8) * 8 + g;
            val = (k < HC) ? g_WcG[((size_t)s * H3C + 2 * HC + f) * HC + k]
                           : Whh[(size_t)(2 * HC + f) * HC + (k - HC)];
        }
        v[e] = val;
    }
    uint32_t hi, lo;
    pack_pair(v[0], v[1], hi, lo);
    g_BHi[idx] = hi;
    g_BLo[idx] = lo;
}

// ---------------- input layer: h = tanh(x @ W_in), fused fragment-image writes ----------------
__global__ void __launch_bounds__(256) k_input(
    const float* __restrict__ x, const float* __restrict__ Win, float* __restrict__ h,
    uint32_t* __restrict__ Hi, uint32_t* __restrict__ Lo)
{
    __shared__ float sw[F_INC * HC];  // [k][c], 32KB
    int tid = threadIdx.x;
    for (int i = tid; i < F_INC * HC; i += 256) sw[i] = Win[i];
    __syncthreads();
    int n = blockIdx.x * 256 + tid;
    if (n >= N_NODESC) return;

    float4 xr[16];
    const float4* xp = (const float4*)(x + (size_t)n * F_INC);
#pragma unroll
    for (int j = 0; j < 16; j++) xr[j] = xp[j];

    int tile = n >> 7, rr = n & 127;
    float* hrow = h + (size_t)n * HC;

#pragma unroll 1
    for (int cg = 0; cg < 8; cg++) {
        float acc[16];
#pragma unroll
        for (int j = 0; j < 16; j++) acc[j] = 0.f;
#pragma unroll
        for (int k4 = 0; k4 < 16; k4++) {
            float4 xv4 = xr[k4];
            float xs[4] = {xv4.x, xv4.y, xv4.z, xv4.w};
#pragma unroll
            for (int kk = 0; kk < 4; kk++) {
                int k = k4 * 4 + kk;
                const float4* wp = (const float4*)(sw + k * HC + cg * 16);
#pragma unroll
                for (int j4 = 0; j4 < 4; j4++) {
                    float4 w = wp[j4];
                    acc[j4 * 4 + 0] += xs[kk] * w.x;
                    acc[j4 * 4 + 1] += xs[kk] * w.y;
                    acc[j4 * 4 + 2] += xs[kk] * w.z;
                    acc[j4 * 4 + 3] += xs[kk] * w.w;
                }
            }
        }
        size_t base = ((size_t)tile * 8 + cg) * 1024;
#pragma unroll
        for (int j = 0; j < 4; j++) {
            float4 o;
            o.x = tanhf(acc[j * 4 + 0]);
            o.y = tanhf(acc[j * 4 + 1]);
            o.z = tanhf(acc[j * 4 + 2]);
            o.w = tanhf(acc[j * 4 + 3]);
            *(float4*)(hrow + cg * 16 + j * 4) = o;
            store_split4(Hi, Lo, base, rr, j * 2, o);
        }
    }
}

// ---------------- bf16x3 mma.sync fused GEMM + GRU, phase-split columns ----------------
// hprev staged via cp.async inside CHUNK 1's group (validated in R15).
__global__ void __launch_bounds__(256, 2) k_gemm(
    const float* __restrict__ hin, float* __restrict__ hout,
    const uint32_t* __restrict__ Bhi, const uint32_t* __restrict__ Blo,
    const uint32_t* __restrict__ HhiIn, const uint32_t* __restrict__ HloIn,
    uint32_t* __restrict__ HhiOut, uint32_t* __restrict__ HloOut,
    const float* __restrict__ bih, const float* __restrict__ bhh,
    const void* __restrict__ batch, int write_img)
{
    extern __shared__ uint32_t smu[];  // 3 stages x STAGE_W | hp [128][36] floats
    __shared__ float sbias[4][32];

    const int tid = threadIdx.x;
    const int lane = tid & 31;
    const int warp = tid >> 5;
    const int warpM = warp & 1;
    const int warpN = warp >> 1;
    const int tile = blockIdx.x;
    const int row0 = tile * 128;
    const int ys = blockIdx.y;
    float* sHp = (float*)(smu + 3 * STAGE_W);

    if (tid < 32) {
        int f = ys * 32 + tid;
        sbias[0][tid] = bih[f] + bhh[f];
        sbias[1][tid] = bih[HC + f] + bhh[HC + f];
        sbias[2][tid] = bih[2 * HC + f];
        sbias[3][tid] = bhh[2 * HC + f];
    }

    const uint32_t* Bh = Bhi + (size_t)ys * 16 * BIMG_KT_W;
    const uint32_t* Bl = Blo + (size_t)ys * 16 * BIMG_KT_W;
    const uint32_t smem_base = smem_u32(smu);
    const uint32_t hp_base = smem_base + (3 * STAGE_W) * 4;

    auto issue = [&](int c) {
        uint32_t d = smem_base + ((c % 3) * STAGE_W) * 4;
#pragma unroll
        for (int kk = 0; kk < 2; kk++) {
            int kt = 2 * c + kk;
            const uint32_t *ah, *al;
            if (kt < 8) {
                ah = g_AHi + ((size_t)tile * 8 + kt) * 1024;
                al = g_ALo + ((size_t)tile * 8 + kt) * 1024;
            } else {
                ah = HhiIn + ((size_t)tile * 8 + (kt - 8)) * 1024;
                al = HloIn + ((size_t)tile * 8 + (kt - 8)) * 1024;
            }
            cpasync16(d + kk * 4096 + tid * 16,        ah + tid * 4);
            cpasync16(d + 8192 + kk * 4096 + tid * 16, al + tid * 4);
            if (tid < 192) {
                cpasync16(d + 16384 + kk * 3072 + tid * 16, Bh + (size_t)kt * BIMG_KT_W + tid * 4);
                cpasync16(d + 22528 + kk * 3072 + tid * 16, Bl + (size_t)kt * BIMG_KT_W + tid * 4);
            }
        }
        if (c == 1) {
            // hprev block (drained by the c=1 wait; hides behind chunk-0 compute)
#pragma unroll
            for (int rep = 0; rep < 4; rep++) {
                int idx = tid + rep * 256;       // 0..1023
                int row = idx >> 3, ch = idx & 7;
                int grow = row0 + row;
                if (grow >= N_NODESC) grow = N_NODESC - 1;  // clamp: finite, row-local
                cpasync16(hp_base + (row * 36 + ch * 4) * 4,
                          hin + (size_t)grow * HC + ys * 32 + ch * 4);
            }
        }
        cp_commit();
    };

    float acc_rz0[4][4], acc_rz1[4][4], acc_in[4][4], acc_hn[4][4];
#pragma unroll
    for (int mt = 0; mt < 4; mt++)
#pragma unroll
        for (int r = 0; r < 4; r++) {
            acc_rz0[mt][r] = 0.f; acc_rz1[mt][r] = 0.f;
            acc_in[mt][r] = 0.f;  acc_hn[mt][r] = 0.f;
        }

    issue(0);
    issue(1);

    for (int c = 0; c < 8; c++) {
        if (c < 7) cp_wait1();
        else cp_wait0();
        __syncthreads();
        if (c <= 5) issue(c + 2);

        const uint32_t* st = smu + (c % 3) * STAGE_W;
        bool ph0 = (c < 4);
#pragma unroll
        for (int kk = 0; kk < 2; kk++) {
            const uint32_t* Ahw = st + kk * 1024;
            const uint32_t* Alw = st + 2048 + kk * 1024;
            const uint32_t* Bhw = st + 4096 + kk * BIMG_KT_W;
            const uint32_t* Blw = st + 5632 + kk * BIMG_KT_W;

            uint2 rz0h = *(const uint2*)(Bhw + (2 * warpN) * 64 + lane * 2);
            uint2 rz0l = *(const uint2*)(Blw + (2 * warpN) * 64 + lane * 2);
            uint2 rz1h = *(const uint2*)(Bhw + (2 * warpN + 1) * 64 + lane * 2);
            uint2 rz1l = *(const uint2*)(Blw + (2 * warpN + 1) * 64 + lane * 2);
            uint2 xh   = *(const uint2*)(Bhw + (8 + warpN) * 64 + lane * 2);
            uint2 xl   = *(const uint2*)(Blw + (8 + warpN) * 64 + lane * 2);
#pragma unroll
            for (int mt = 0; mt < 4; mt++) {
                int rb = warpM * 4 + mt;
                uint4 ah = *(const uint4*)(Ahw + rb * 128 + lane * 4);
                uint4 al = *(const uint4*)(Alw + rb * 128 + lane * 4);
                mma3(acc_rz0[mt], ah, al, rz0h, rz0l);
                mma3(acc_rz1[mt], ah, al, rz1h, rz1l);
                if (ph0) mma3(acc_in[mt], ah, al, xh, xl);
                else     mma3(acc_hn[mt], ah, al, xh, xl);
            }
        }
    }
    __syncthreads();   // all compute done before sOut aliases pipeline smem

    // ---------------- fused GRU epilogue (phase-split layout) ----------------
    float* sOut = (float*)smu;  // [128][36], aliases stage smem (hp block untouched)
    const int g = lane >> 2;
    const int tI = lane & 3;
    const bool use1 = (tI >= 2);

#pragma unroll
    for (int mt = 0; mt < 4; mt++) {
        int rowl = warpM * 64 + mt * 16 + g;
#pragma unroll
        for (int e = 0; e < 2; e++) {
            int u = 2 * tI + e;
            int src = g * 4 + (u & 3);
            float v0[4], v1[4];
#pragma unroll
            for (int i = 0; i < 4; i++) {
                v0[i] = __shfl_sync(0xffffffffu, acc_rz0[mt][i], src);
                v1[i] = __shfl_sync(0xffffffffu, acc_rz1[mt][i], src);
            }
            float Sr_a = use1 ? v1[0] : v0[0];
            float Sz_a = use1 ? v1[1] : v0[1];
            float Sr_b = use1 ? v1[2] : v0[2];
            float Sz_b = use1 ? v1[3] : v0[3];
            float in_a = acc_in[mt][e],     in_b = acc_in[mt][2 + e];
            float hn_a = acc_hn[mt][e],     hn_b = acc_hn[mt][2 + e];
            int fl = warpN * 8 + u;
            float hpa = sHp[rowl * 36 + fl];
            float hpb = sHp[(rowl + 8) * 36 + fl];
            float ra = sigf(Sr_a + sbias[0][fl]);
            float za = sigf(Sz_a + sbias[1][fl]);
            float na = tanhfast(in_a + sbias[2][fl] + ra * (hn_a + sbias[3][fl]));
            float rb2 = sigf(Sr_b + sbias[0][fl]);
            float zb = sigf(Sz_b + sbias[1][fl]);
            float nb2 = tanhfast(in_b + sbias[2][fl] + rb2 * (hn_b + sbias[3][fl]));
            sOut[rowl * 36 + fl]       = (1.f - za) * na + za * hpa;
            sOut[(rowl + 8) * 36 + fl] = (1.f - zb) * nb2 + zb * hpb;
        }
    }
    __syncthreads();

    // hout (fp32) writeback / pool accumulation
#pragma unroll
    for (int rep = 0; rep < 4; rep++) {
        int idx = tid + rep * 256;
        int row = idx >> 3, q = idx & 7;
        int grow = row0 + row;
        if (grow < N_NODESC) {
            float4 o = *(const float4*)(sOut + row * 36 + q * 4);
            if (write_img) {
                *(float4*)(hout + (size_t)grow * HC + ys * 32 + q * 4) = o;
            } else {
                int gidx = load_idx(batch, grow, g_is64);
                red4(&g_sums[gidx * HC + ys * 32 + q * 4], o);
            }
        }
    }

    // coalesced h-image writeback from sOut (2 kt blocks owned by this CTA)
    if (write_img) {
        int gq = (tid & 31) >> 2;
        int pm = tid & 3;
        int rb2 = tid >> 5;
        int rowA = rb2 * 16 + gq;
        int rowB = rowA + 8;
#pragma unroll
        for (int kb = 0; kb < 2; kb++) {
            int fb = kb * 16;
            float a0v = sOut[rowA * 36 + fb + 2 * pm],     a1v = sOut[rowA * 36 + fb + 2 * pm + 1];
            float b0v = sOut[rowB * 36 + fb + 2 * pm],     b1v = sOut[rowB * 36 + fb + 2 * pm + 1];
            float c0v = sOut[rowA * 36 + fb + 2 * pm + 8], c1v = sOut[rowA * 36 + fb + 2 * pm + 9];
            float d0v = sOut[rowB * 36 + fb + 2 * pm + 8], d1v = sOut[rowB * 36 + fb + 2 * pm + 9];
            uint4 hi4, lo4;
            pack_pair(a0v, a1v, hi4.x, lo4.x);
            pack_pair(b0v, b1v, hi4.y, lo4.y);
            pack_pair(c0v, c1v, hi4.z, lo4.z);
            pack_pair(d0v, d1v, hi4.w, lo4.w);
            size_t base = ((size_t)tile * 8 + ys * 2 + kb) * 1024;
            *(uint4*)(HhiOut + base + tid * 4) = hi4;
            *(uint4*)(HloOut + base + tid * 4) = lo4;
        }
    }
}

// ---------------- output ----------------
__global__ void k_out(const float* __restrict__ Wp, const float* __restrict__ bp,
                      float* __restrict__ out) {
    int g = blockIdx.x;
    int t = threadIdx.x;  // 128
    float c = fmaxf(g_cnt[g], 1.0f);
    float pooled = g_sums[g * HC + t] / c;
    float v = fmaxf(pooled, 0.f) * Wp[t];
    __shared__ float red[4];
#pragma unroll
    for (int o = 16; o > 0; o >>= 1) v += __shfl_down_sync(0xffffffff, v, o);
    if ((t & 31) == 0) red[t >> 5] = v;
    __syncthreads();
    if (t == 0) out[g] = red[0] + red[1] + red[2] + red[3] + bp[0];
}

// ---------------- launch ----------------
extern "C" void kernel_launch(void* const* d_in, const int* in_sizes, int n_in,
                              void* d_out, int out_size) {
    const float* x    = (const float*)d_in[0];
    const void*  ei   = d_in[1];
    const void*  batch= d_in[2];
    const float* W_in = (const float*)d_in[3];
    const float* W_mp = (const float*)d_in[4];
    const float* W_ih = (const float*)d_in[5];
    const float* W_hh = (const float*)d_in[6];
    const float* b_ih = (const float*)d_in[7];
    const float* b_hh = (const float*)d_in[8];
    const float* W_p  = (const float*)d_in[9];
    const float* b_p  = (const float*)d_in[10];
    float* out = (float*)d_out;

    void *hA, *hB, *sumsPtr, *cntPtr, *degPtr, *curPtr;
    void *bHiP, *bLoP, *hHiP, *hLoP;
    cudaGetSymbolAddress(&hA, g_hA);
    cudaGetSymbolAddress(&hB, g_hB);
    cudaGetSymbolAddress(&sumsPtr, g_sums);
    cudaGetSymbolAddress(&cntPtr, g_cnt);
    cudaGetSymbolAddress(&degPtr, g_deg);
    cudaGetSymbolAddress(&curPtr, g_cursor);
    cudaGetSymbolAddress(&bHiP, g_BHi);
    cudaGetSymbolAddress(&bLoP, g_BLo);
    cudaGetSymbolAddress(&hHiP, g_HHi);
    cudaGetSymbolAddress(&hLoP, g_HLo);
    const uint32_t* BHi = (const uint32_t*)bHiP;
    const uint32_t* BLo = (const uint32_t*)bLoP;
    uint32_t* HHi = (uint32_t*)hHiP;  // [2][AIMG_WORDS]
    uint32_t* HLo = (uint32_t*)hLoP;

    cudaFuncSetAttribute(k_gemm, cudaFuncAttributeMaxDynamicSharedMemorySize, SMEM_DYN);

    k_detect<<<1, 256>>>((const int*)ei);

    // pooled-sum scratch + per-graph counts
    cudaMemsetAsync(sumsPtr, 0, (size_t)N_GRAPHSC * HC * sizeof(float), 0);
    cudaMemsetAsync(cntPtr, 0, (size_t)N_GRAPHSC * sizeof(float), 0);
    k_cnt<<<(N_NODESC + 255) / 256, 256>>>(batch);

    // CSR build
    cudaMemsetAsync(degPtr, 0, N_NODESC * sizeof(int), 0);
    cudaMemsetAsync(curPtr, 0, N_NODESC * sizeof(int), 0);
    k_deg<<<(N_EDGESC / 4 + 255) / 256, 256>>>(ei);
    k_scan1<<<NSCANB, 256>>>();
    k_scan2<<<1, 32>>>();
    k_scan3<<<NSCANB, 256>>>();
    k_fill<<<(N_EDGESC + 255) / 256, 256>>>(ei);

    // weights
    k_prep_wc<<<(STEPSC * H3C * HC + 255) / 256, 256>>>(W_mp, W_ih);
    k_prep_bimg<<<(STEPSC * BIMG_STEP_W + 255) / 256, 256>>>(W_hh);

    // input layer (writes h AND the step-0 h fragment images)
    k_input<<<(N_NODESC + 255) / 256, 256>>>(x, W_in, (float*)hA, HHi, HLo);

    float* hcur = (float*)hA;
    float* hnext = (float*)hB;
    for (int s = 0; s < STEPSC; s++) {
        int pin = s & 1, pout = (s + 1) & 1;
        k_gather<<<N_NODESC / 16, 512>>>(hcur);
        dim3 grid(NTILES, 4);
        k_gemm<<<grid, 256, SMEM_DYN>>>(
            hcur, hnext,
            BHi + (size_t)s * BIMG_STEP_W, BLo + (size_t)s * BIMG_STEP_W,
            HHi + (size_t)pin * AIMG_WORDS, HLo + (size_t)pin * AIMG_WORDS,
            HHi + (size_t)pout * AIMG_WORDS, HLo + (size_t)pout * AIMG_WORDS,
            b_ih, b_hh, batch, (s < STEPSC - 1) ? 1 : 0);
        float* tmp = hcur; hcur = hnext; hnext = tmp;
    }
    k_out<<<N_GRAPHSC, 128>>>(W_p, b_p, out);
}